// round 12
// baseline (speedup 1.0000x reference)
#include <cuda_runtime.h>
#include <math.h>
#include <stdint.h>

#define BS2   2
#define NN    8192
#define NPT   128
#define CC    128
#define M_TOT 8192        // NPT*64 per batch
#define MG    16384       // total corners
#define NBOX  256         // BS2*NPT
#define CAP   8192        // max candidates per box
#define FULLM 0xffffffffu

// ---------------- device scratch ----------------
static __device__ float g_p2[(size_t)BS2*NN];
static __device__ float g_rel[(size_t)MG*3];
static __device__ float g_cor[(size_t)MG*3];
static __device__ int   g_nni[(size_t)MG*3];
static __device__ float g_nnw[(size_t)MG*3];
static __device__ float g_ctr[NBOX*3];
static __device__ float g_md[NBOX];
static __device__ float g_R2[NBOX];
static __device__ float4 g_cpts[(size_t)NBOX*CAP];
static __device__ int    g_cidx[(size_t)NBOX*CAP];
static __device__ int    g_ccnt[NBOX];
static __device__ float g_w1T[128*128];                 // [k][o]
static __device__ float g_w2T[128*256];                 // [k][o]
static __device__ float g_G[(size_t)BS2*NN*128];        // [b][n][o] = W1f . f
static __device__ float g_h1T[(size_t)128*MG];          // [c][m]
static __device__ float g_pool[(size_t)BS2*256*NPT];    // [b][o][p]
static __device__ float g_z0[(size_t)BS2*128*NPT];
static __device__ float g_z1[(size_t)BS2*128*NPT];

__device__ __forceinline__ float tf32r(float x) {
    uint32_t u; asm("cvt.rna.tf32.f32 %0, %1;" : "=r"(u) : "f"(x));
    return __uint_as_float(u);
}

__device__ __forceinline__ void mma_tf32(float c[4], const uint32_t a[4], const uint32_t b[2]) {
    asm volatile(
        "mma.sync.aligned.m16n8k8.row.col.f32.tf32.tf32.f32 "
        "{%0,%1,%2,%3}, {%4,%5,%6,%7}, {%8,%9}, {%0,%1,%2,%3};\n"
        : "+f"(c[0]), "+f"(c[1]), "+f"(c[2]), "+f"(c[3])
        : "r"(a[0]), "r"(a[1]), "r"(a[2]), "r"(a[3]), "r"(b[0]), "r"(b[1]));
}

// ---------------- setup_a: decode + p2 + per-box center/halfdiag ----------------
__global__ void setup_a_kernel(const float* __restrict__ cand,
                               const float* __restrict__ off,
                               const float* __restrict__ acls,
                               const float* __restrict__ ares,
                               const float* __restrict__ oxyz)
{
    int bx = blockIdx.x, tid = threadIdx.x;
    if (bx < 64) {
        int t = bx*256 + tid;                        // 16384 = b*8192 + p*64 + k
        int k  = t & 63;
        int bp = t >> 6;
        const float* a = acls + bp*12;
        float best = a[0]; int bi = 0;
        #pragma unroll
        for (int j = 1; j < 12; j++) { float v = a[j]; if (v > best) { best = v; bi = j; } }
        float res = ares[bp*12 + bi];
        const float PI_F = 3.14159265358979323846f;
        float ang = (float)bi * (float)(2.0*3.14159265358979323846/12.0) + res;
        float heading = (ang > PI_F) ? (ang - 2.0f*PI_F) : ang;
        float s, c; sincosf(heading, &s, &c);
        const float* o6 = off + bp*6;
        float cx = cand[bp*3+0] + o6[0];
        float cy = cand[bp*3+1] + o6[1];
        float cz = cand[bp*3+2] + o6[2];
        float lx = fmaxf(o6[3]*2.0f, 0.1f);
        float ly = fmaxf(o6[4]*2.0f, 0.1f);
        float lz = fmaxf(o6[5]*2.0f, 0.1f);
        if (k == 0) {
            g_ctr[bp*3+0] = cx; g_ctr[bp*3+1] = cy; g_ctr[bp*3+2] = cz;
            g_md[bp] = sqrtf(lx*lx + ly*ly + lz*lz);
        }
        float gv[4] = {-1.0f, -1.0f/3.0f, 1.0f/3.0f, 1.0f};
        float gx = gv[(k>>4)&3] * lx;
        float gy = gv[(k>>2)&3] * ly;
        float gz = gv[k&3]      * lz;
        float rx = gx*c - gy*s;
        float ry = gx*s + gy*c;
        float rz = gz;
        size_t b3 = (size_t)t*3;
        g_rel[b3+0] = rx; g_rel[b3+1] = ry; g_rel[b3+2] = rz;
        g_cor[b3+0] = rx + cx; g_cor[b3+1] = ry + cy; g_cor[b3+2] = rz + cz;
    } else {
        int t = (bx-64)*256 + tid;
        float x = oxyz[t*3], y = oxyz[t*3+1], z = oxyz[t*3+2];
        g_p2[t] = x*x + y*y + z*z;
    }
}

// values-only top-3 insert
#define INSERT3V(tt, d0, d1, d2)                               \
    do {                                                        \
        bool q2 = (tt) < (d2), q1 = (tt) < (d1), q0 = (tt) < (d0); \
        (d2) = q1 ? (d1) : (q2 ? (tt) : (d2));                  \
        (d1) = q0 ? (d0) : (q1 ? (tt) : (d1));                  \
        (d0) = q0 ? (tt) : (d0);                                \
    } while (0)

// ---------------- center3: exact d3 per box center -> pruning radius^2 ----------------
__global__ void center3_kernel(const float* __restrict__ oxyz)
{
    int tid = threadIdx.x, lane = tid & 31, wid = tid >> 5;
    int cid = blockIdx.x*8 + wid;                // 0..255
    int b = cid >> 7;
    const float* O = oxyz + (size_t)b*NN*3;
    const float* Q = g_p2 + (size_t)b*NN;
    float cx = g_ctr[cid*3+0], cy = g_ctr[cid*3+1], cz = g_ctr[cid*3+2];
    float c2 = cx*cx + cy*cy + cz*cz;
    float ax = -2.0f*cx, ay = -2.0f*cy, az = -2.0f*cz;
    float d0 = 1e30f, d1 = 1e30f, d2v = 1e30f;
    for (int n = lane; n < NN; n += 32) {
        float t = Q[n] + c2;
        t = fmaf(ax, O[n*3+0], t);
        t = fmaf(ay, O[n*3+1], t);
        t = fmaf(az, O[n*3+2], t);
        if (t < d2v) INSERT3V(t, d0, d1, d2v);
    }
    #pragma unroll
    for (int offi = 16; offi; offi >>= 1) {
        float e0 = __shfl_xor_sync(FULLM, d0, offi);
        float e1 = __shfl_xor_sync(FULLM, d1, offi);
        float e2 = __shfl_xor_sync(FULLM, d2v, offi);
        INSERT3V(e0, d0, d1, d2v);
        INSERT3V(e1, d0, d1, d2v);
        INSERT3V(e2, d0, d1, d2v);
    }
    if (lane == 0) {
        float r = sqrtf(fmaxf(d2v, 0.0f)) + 2.0f*g_md[cid] + 1e-2f;
        g_R2[cid] = r*r*1.0001f + 1e-3f;
    }
}

// ---------------- compact: per-box ordered candidate list ----------------
__global__ void __launch_bounds__(256) compact_kernel(const float* __restrict__ oxyz)
{
    __shared__ int s_warp[8];
    __shared__ int s_base;
    int box = blockIdx.x;                         // 0..255
    int b = box >> 7;
    int tid = threadIdx.x, lane = tid & 31, wid = tid >> 5;
    const float* O = oxyz + (size_t)b*NN*3;
    const float* Q = g_p2 + (size_t)b*NN;
    float cx = g_ctr[box*3+0], cy = g_ctr[box*3+1], cz = g_ctr[box*3+2];
    float c2 = cx*cx + cy*cy + cz*cz;
    float ax = -2.0f*cx, ay = -2.0f*cy, az = -2.0f*cz;
    float R2 = g_R2[box];
    float4* CP = g_cpts + (size_t)box*CAP;
    int*    CI = g_cidx + (size_t)box*CAP;
    if (tid == 0) s_base = 0;
    __syncthreads();
    for (int t0 = 0; t0 < NN; t0 += 256) {
        int n = t0 + tid;
        float x = O[n*3+0], y = O[n*3+1], z = O[n*3+2];
        float p2 = Q[n];
        float d = p2 + c2;
        d = fmaf(ax, x, d); d = fmaf(ay, y, d); d = fmaf(az, z, d);
        bool keep = d <= R2;
        unsigned mask = __ballot_sync(FULLM, keep);
        if (lane == 0) s_warp[wid] = __popc(mask);
        __syncthreads();
        int prev = 0, tot = 0;
        #pragma unroll
        for (int w = 0; w < 8; w++) {
            int cn = s_warp[w];
            if (w < wid) prev += cn;
            tot += cn;
        }
        int pos = s_base + prev + __popc(mask & ((1u << lane) - 1u));
        if (keep) {
            CP[pos] = make_float4(x, y, z, p2);
            CI[pos] = n;
        }
        __syncthreads();
        if (tid == 0) s_base += tot;
        __syncthreads();
    }
    if (tid == 0) g_ccnt[box] = s_base;
}

// warp-uniform insert with index
#define INSERT3(tt, nn_, d0, i0, d1, i1, d2, i2)               \
    do {                                                        \
        bool q2 = (tt) < (d2), q1 = (tt) < (d1), q0 = (tt) < (d0); \
        (d2) = q1 ? (d1) : (q2 ? (tt) : (d2));                  \
        (i2) = q1 ? (i1) : (q2 ? (nn_) : (i2));                 \
        (d1) = q0 ? (d0) : (q1 ? (tt) : (d1));                  \
        (i1) = q0 ? (i0) : (q1 ? (nn_) : (i1));                 \
        (d0) = q0 ? (tt) : (d0);                                \
        (i0) = q0 ? (nn_) : (i0);                               \
    } while (0)

#define DRAIN(bal, tval, d0, i0, d1, i1, d2, i2, nbase)        \
    while (bal) {                                               \
        int s = __ffs(bal) - 1; bal &= bal - 1;                 \
        float tt = __shfl_sync(FULLM, tval, s);                 \
        int nn_ = (nbase) + s;                                  \
        INSERT3(tt, nn_, d0, i0, d1, i1, d2, i2);               \
    }

// write corner result: positions -> indices, exact fp32 weights
__device__ __forceinline__ void write_top3_cand(int lane, const float* __restrict__ O,
                                                const int* __restrict__ CI,
                                                size_t cb, int p0, int p1, int p2)
{
    if (lane == 0) {
        float cx = g_cor[cb+0], cy = g_cor[cb+1], cz = g_cor[cb+2];
        int win[3] = {CI[p0], CI[p1], CI[p2]};
        float w[3], ssum = 0.0f;
        #pragma unroll
        for (int r = 0; r < 3; r++) {
            const float* P = O + (size_t)win[r]*3;
            float dx = P[0]-cx, dy = P[1]-cy, dz = P[2]-cz;
            float d = sqrtf(dx*dx + dy*dy + dz*dz);
            w[r] = 1.0f / (d + 1e-8f);
            ssum += w[r];
        }
        float inv = 1.0f/ssum;
        #pragma unroll
        for (int r = 0; r < 3; r++) { g_nni[cb+r] = win[r]; g_nnw[cb+r] = w[r]*inv; }
    }
}

// ---------------- stage D: top-3 over candidates, warp = 4 corners, vote-gated ----------------
__global__ void __launch_bounds__(256) threenn_cand_kernel(const float* __restrict__ oxyz)
{
    int tid = threadIdx.x, lane = tid & 31, wid = tid >> 5;
    int box = blockIdx.x >> 1;                    // 2 blocks per box
    int b = box >> 7, p = box & 127;
    int g = (blockIdx.x & 1)*8 + wid;             // corner group 0..15
    int k0 = g*4;
    const float* O = oxyz + (size_t)b*NN*3;
    size_t cb = ((size_t)b*M_TOT + p*64 + k0)*3;

    float c2A, axA, ayA, azA, c2B, axB, ayB, azB;
    float c2C, axC, ayC, azC, c2D, axD, ayD, azD;
    {
        float x, y, z;
        x = g_cor[cb+0];  y = g_cor[cb+1];  z = g_cor[cb+2];
        c2A = x*x+y*y+z*z; axA = -2.0f*x; ayA = -2.0f*y; azA = -2.0f*z;
        x = g_cor[cb+3];  y = g_cor[cb+4];  z = g_cor[cb+5];
        c2B = x*x+y*y+z*z; axB = -2.0f*x; ayB = -2.0f*y; azB = -2.0f*z;
        x = g_cor[cb+6];  y = g_cor[cb+7];  z = g_cor[cb+8];
        c2C = x*x+y*y+z*z; axC = -2.0f*x; ayC = -2.0f*y; azC = -2.0f*z;
        x = g_cor[cb+9];  y = g_cor[cb+10]; z = g_cor[cb+11];
        c2D = x*x+y*y+z*z; axD = -2.0f*x; ayD = -2.0f*y; azD = -2.0f*z;
    }

    int cnt = g_ccnt[box];
    const float4* CP = g_cpts + (size_t)box*CAP;
    const int*    CI = g_cidx + (size_t)box*CAP;

    float dA0=1e30f,dA1=1e30f,dA2=1e30f; int iA0=0,iA1=0,iA2=0;
    float dB0=1e30f,dB1=1e30f,dB2=1e30f; int iB0=0,iB1=0,iB2=0;
    float dC0=1e30f,dC1=1e30f,dC2=1e30f; int iC0=0,iC1=0,iC2=0;
    float dD0=1e30f,dD1=1e30f,dD2=1e30f; int iD0=0,iD1=0,iD2=0;

    for (int base = 0; base < cnt; base += 32) {
        int pos = base + lane;
        bool valid = pos < cnt;
        float4 pt = CP[valid ? pos : (cnt - 1)];
        if (!valid) pt.w = 1e30f;                 // t >= 1e30 -> never inserted (strict <)
        float tA = fmaf(axA, pt.x, pt.w + c2A); tA = fmaf(ayA, pt.y, tA); tA = fmaf(azA, pt.z, tA);
        float tB = fmaf(axB, pt.x, pt.w + c2B); tB = fmaf(ayB, pt.y, tB); tB = fmaf(azB, pt.z, tB);
        float tC = fmaf(axC, pt.x, pt.w + c2C); tC = fmaf(ayC, pt.y, tC); tC = fmaf(azC, pt.z, tC);
        float tD = fmaf(axD, pt.x, pt.w + c2D); tD = fmaf(ayD, pt.y, tD); tD = fmaf(azD, pt.z, tD);
        bool hit = (tA < dA2) | (tB < dB2) | (tC < dC2) | (tD < dD2);
        if (__any_sync(FULLM, hit)) {
            unsigned bal;
            bal = __ballot_sync(FULLM, tA < dA2); DRAIN(bal, tA, dA0, iA0, dA1, iA1, dA2, iA2, base);
            bal = __ballot_sync(FULLM, tB < dB2); DRAIN(bal, tB, dB0, iB0, dB1, iB1, dB2, iB2, base);
            bal = __ballot_sync(FULLM, tC < dC2); DRAIN(bal, tC, dC0, iC0, dC1, iC1, dC2, iC2, base);
            bal = __ballot_sync(FULLM, tD < dD2); DRAIN(bal, tD, dD0, iD0, dD1, iD1, dD2, iD2, base);
        }
    }
    write_top3_cand(lane, O, CI, cb,     iA0, iA1, iA2);
    write_top3_cand(lane, O, CI, cb + 3, iB0, iB1, iB2);
    write_top3_cand(lane, O, CI, cb + 6, iC0, iC1, iC2);
    write_top3_cand(lane, O, CI, cb + 9, iD0, iD1, iD2);
}

// ---------------- setup_b: transpose W1f / W2 ----------------
__global__ void setup_b_kernel(const float* __restrict__ w1, const float* __restrict__ w2)
{
    int bx = blockIdx.x, tid = threadIdx.x;
    if (bx < 64) {
        int t = bx*256 + tid;                        // 16384 = k*128+o
        int o = t & 127, k = t >> 7;
        g_w1T[t] = w1[o*131 + 3 + k];
    } else {
        int t = (bx-64)*256 + tid;                   // 32768 = k*256+o
        int o = t & 255, k = t >> 8;
        g_w2T[t] = w2[o*128 + k];
    }
}

// ---------------- gemm_G: 128n x 64o, BK=16, 8x4, double-buffered (proven) ----------------
__global__ void __launch_bounds__(256) gemmG_kernel(const float* __restrict__ feat)
{
    __shared__ float Ns[2][16][132];
    __shared__ float Os[2][16][64];
    int n0 = blockIdx.x*128, o0 = blockIdx.y*64, b = blockIdx.z;
    int tid = threadIdx.x;
    int kr  = tid >> 4;
    int nc  = (tid & 15)*8;
    int oc  = (tid & 15)*4;
    int tr  = (tid >> 4)*8;
    int tc  = (tid & 15)*4;
    const float* F = feat + (size_t)b*CC*NN;

    float acc[8][4] = {};
    float4 na0, na1, nb;
    na0 = *(const float4*)&F[(size_t)kr*NN + n0 + nc];
    na1 = *(const float4*)&F[(size_t)kr*NN + n0 + nc + 4];
    nb  = *(const float4*)&g_w1T[kr*128 + o0 + oc];
    *(float4*)&Ns[0][kr][nc]   = na0;
    *(float4*)&Ns[0][kr][nc+4] = na1;
    *(float4*)&Os[0][kr][oc]   = nb;
    __syncthreads();
    int buf = 0;
    #pragma unroll 1
    for (int kb = 0; kb < 8; kb++) {
        bool has = kb < 7;
        if (has) {
            int kk = (kb+1)*16 + kr;
            na0 = *(const float4*)&F[(size_t)kk*NN + n0 + nc];
            na1 = *(const float4*)&F[(size_t)kk*NN + n0 + nc + 4];
            nb  = *(const float4*)&g_w1T[kk*128 + o0 + oc];
        }
        #pragma unroll
        for (int k = 0; k < 16; k++) {
            float4 a0 = *(const float4*)&Ns[buf][k][tr];
            float4 a1 = *(const float4*)&Ns[buf][k][tr+4];
            float4 bq = *(const float4*)&Os[buf][k][tc];
            float ar[8] = {a0.x,a0.y,a0.z,a0.w,a1.x,a1.y,a1.z,a1.w};
            float br[4] = {bq.x,bq.y,bq.z,bq.w};
            #pragma unroll
            for (int i = 0; i < 8; i++)
                #pragma unroll
                for (int j = 0; j < 4; j++)
                    acc[i][j] = fmaf(ar[i], br[j], acc[i][j]);
        }
        if (has) {
            int nbuf = buf^1;
            *(float4*)&Ns[nbuf][kr][nc]   = na0;
            *(float4*)&Ns[nbuf][kr][nc+4] = na1;
            *(float4*)&Os[nbuf][kr][oc]   = nb;
            __syncthreads();
            buf = nbuf;
        }
    }
    float* Gp = g_G + ((size_t)b*NN + n0 + tr)*128 + o0 + tc;
    #pragma unroll
    for (int i = 0; i < 8; i++) {
        float4 v = {acc[i][0], acc[i][1], acc[i][2], acc[i][3]};
        *(float4*)(Gp + (size_t)i*128) = v;
    }
}

// ---------------- combine v2: block = 32 corners, coalesced h1T row writes ----------------
__global__ void __launch_bounds__(256) combine_kernel(const float* __restrict__ w1,
                                                      const float* __restrict__ b1)
{
    __shared__ float wr0[128], wr1[128], wr2[128], sb[128];
    __shared__ float tr[128][33];
    int tid = threadIdx.x, lane = tid & 31, wid = tid >> 5;
    if (tid < 128) {
        const float* wrow = w1 + tid*131;
        wr0[tid] = wrow[0]; wr1[tid] = wrow[1]; wr2[tid] = wrow[2];
        sb[tid]  = b1[tid];
    }
    __syncthreads();
    int m0 = blockIdx.x*32;
    #pragma unroll 1
    for (int cc = 0; cc < 4; cc++) {
        int ml = wid*4 + cc;                         // 0..31 local corner
        int m  = m0 + ml;
        int b = m >> 13, mb = m & 8191;
        size_t base3 = ((size_t)b*M_TOT + mb)*3;
        int i0 = g_nni[base3+0], i1 = g_nni[base3+1], i2 = g_nni[base3+2];
        float w0 = g_nnw[base3+0], w1w = g_nnw[base3+1], w2w = g_nnw[base3+2];
        float rx = g_rel[(size_t)m*3+0], ry = g_rel[(size_t)m*3+1], rz = g_rel[(size_t)m*3+2];
        const float* G0 = g_G + ((size_t)b*NN + i0)*128;
        const float* G1 = g_G + ((size_t)b*NN + i1)*128;
        const float* G2 = g_G + ((size_t)b*NN + i2)*128;
        int c0 = lane*4;
        float4 a  = *(const float4*)(G0 + c0);
        float4 bq = *(const float4*)(G1 + c0);
        float4 cq = *(const float4*)(G2 + c0);
        float va[4] = {a.x,a.y,a.z,a.w};
        float vb[4] = {bq.x,bq.y,bq.z,bq.w};
        float vc[4] = {cq.x,cq.y,cq.z,cq.w};
        #pragma unroll
        for (int j = 0; j < 4; j++) {
            int o = c0 + j;
            float acc = w0*va[j] + w1w*vb[j] + w2w*vc[j];
            acc = fmaf(rx, wr0[o], acc);
            acc = fmaf(ry, wr1[o], acc);
            acc = fmaf(rz, wr2[o], acc);
            tr[o][ml] = fmaxf(acc + sb[o], 0.0f);
        }
    }
    __syncthreads();
    int c = tid >> 1, base = (tid & 1)*16;
    float* dst = &g_h1T[(size_t)c*MG + m0 + base];
    #pragma unroll
    for (int q = 0; q < 4; q++) {
        float4 v = {tr[c][base+q*4+0], tr[c][base+q*4+1], tr[c][base+q*4+2], tr[c][base+q*4+3]};
        *(float4*)(dst + q*4) = v;
    }
}

// ---------------- gemm2 (tf32 tensor-core) + fused relu + maxpool over 64 ----------------
__global__ void __launch_bounds__(256) gemm2_pool_kernel(const float* __restrict__ bias)
{
    __shared__ float As[2][16][132];     // [k][m], padded
    __shared__ float Bs[2][16][68];      // [k][o], padded
    __shared__ int spool[128];           // [2 pool-groups][64 o]
    int m0 = blockIdx.x*128, o0 = blockIdx.y*64;
    int tid = threadIdx.x, lane = tid & 31, wid = tid >> 5;
    int wm = wid >> 1, wn = wid & 1;
    int kr = tid >> 4, c16 = tid & 15;
    if (tid < 128) spool[tid] = 0;

    float acc[2][4][4] = {};

    {
        const float* ap = &g_h1T[(size_t)kr*MG + m0 + c16*8];
        float4 a0 = *(const float4*)ap;
        float4 a1 = *(const float4*)(ap + 4);
        float* d = &As[0][kr][c16*8];
        d[0]=tf32r(a0.x); d[1]=tf32r(a0.y); d[2]=tf32r(a0.z); d[3]=tf32r(a0.w);
        d[4]=tf32r(a1.x); d[5]=tf32r(a1.y); d[6]=tf32r(a1.z); d[7]=tf32r(a1.w);
        float4 bv = *(const float4*)&g_w2T[kr*256 + o0 + c16*4];
        float* e = &Bs[0][kr][c16*4];
        e[0]=tf32r(bv.x); e[1]=tf32r(bv.y); e[2]=tf32r(bv.z); e[3]=tf32r(bv.w);
    }
    __syncthreads();

    int buf = 0;
    int lk = lane & 3, lr = lane >> 2;
    #pragma unroll 1
    for (int kb = 0; kb < 8; kb++) {
        bool has = kb < 7;
        float4 na0, na1, nb;
        if (has) {
            int kk = (kb+1)*16 + kr;
            const float* ap = &g_h1T[(size_t)kk*MG + m0 + c16*8];
            na0 = *(const float4*)ap;
            na1 = *(const float4*)(ap + 4);
            nb  = *(const float4*)&g_w2T[kk*256 + o0 + c16*4];
        }
        #pragma unroll
        for (int ks = 0; ks < 2; ks++) {
            int klo = ks*8 + lk;
            uint32_t afr[2][4];
            #pragma unroll
            for (int mt = 0; mt < 2; mt++) {
                int mr = wm*32 + mt*16 + lr;
                afr[mt][0] = __float_as_uint(As[buf][klo  ][mr]);
                afr[mt][1] = __float_as_uint(As[buf][klo  ][mr+8]);
                afr[mt][2] = __float_as_uint(As[buf][klo+4][mr]);
                afr[mt][3] = __float_as_uint(As[buf][klo+4][mr+8]);
            }
            uint32_t bfr[4][2];
            #pragma unroll
            for (int nt = 0; nt < 4; nt++) {
                int nr = wn*32 + nt*8 + lr;
                bfr[nt][0] = __float_as_uint(Bs[buf][klo  ][nr]);
                bfr[nt][1] = __float_as_uint(Bs[buf][klo+4][nr]);
            }
            #pragma unroll
            for (int mt = 0; mt < 2; mt++)
                #pragma unroll
                for (int nt = 0; nt < 4; nt++)
                    mma_tf32(acc[mt][nt], afr[mt], bfr[nt]);
        }
        if (has) {
            int nbuf = buf^1;
            float* d = &As[nbuf][kr][c16*8];
            d[0]=tf32r(na0.x); d[1]=tf32r(na0.y); d[2]=tf32r(na0.z); d[3]=tf32r(na0.w);
            d[4]=tf32r(na1.x); d[5]=tf32r(na1.y); d[6]=tf32r(na1.z); d[7]=tf32r(na1.w);
            float* e = &Bs[nbuf][kr][c16*4];
            e[0]=tf32r(nb.x); e[1]=tf32r(nb.y); e[2]=tf32r(nb.z); e[3]=tf32r(nb.w);
            __syncthreads();
            buf = nbuf;
        }
    }

    int grp = wm >> 1;
    #pragma unroll
    for (int nt = 0; nt < 4; nt++) {
        int c0 = wn*32 + nt*8 + (lane & 3)*2;
        float b0v = bias[o0 + c0], b1v = bias[o0 + c0 + 1];
        float p0v = 0.0f, p1v = 0.0f;
        #pragma unroll
        for (int mt = 0; mt < 2; mt++) {
            p0v = fmaxf(p0v, acc[mt][nt][0] + b0v);
            p0v = fmaxf(p0v, acc[mt][nt][2] + b0v);
            p1v = fmaxf(p1v, acc[mt][nt][1] + b1v);
            p1v = fmaxf(p1v, acc[mt][nt][3] + b1v);
        }
        atomicMax(&spool[grp*64 + c0],     __float_as_int(p0v));
        atomicMax(&spool[grp*64 + c0 + 1], __float_as_int(p1v));
    }
    __syncthreads();
    if (tid < 128) {
        int g = tid >> 6, ol = tid & 63;
        int b  = m0 >> 13;
        int p0 = (m0 >> 6) & 127;
        g_pool[((size_t)b*256 + o0 + ol)*NPT + p0 + g] = __int_as_float(spool[g*64 + ol]);
    }
}

// ---------------- fused linear + train-mode BN + relu ----------------
__global__ void lin_bn_kernel(const float* __restrict__ W, const float* __restrict__ bias,
                              const float* __restrict__ gam, const float* __restrict__ bet,
                              int stage)
{
    int o = blockIdx.x, tid = threadIdx.x;            // 256 threads = (b,p)
    int b = tid >> 7, p = tid & 127;
    int K = stage ? 128 : 256;
    const float* X = stage ? g_z0 : g_pool;
    __shared__ float ws[256];
    if (tid < K) ws[tid] = W[o*K + tid];
    __syncthreads();
    const float* Xb = X + (size_t)b*K*NPT + p;
    float acc = bias[o];
    #pragma unroll 8
    for (int c = 0; c < K; c++) acc = fmaf(ws[c], Xb[(size_t)c*NPT], acc);
    __shared__ float red[256];
    red[tid] = acc; __syncthreads();
    #pragma unroll
    for (int s = 128; s > 0; s >>= 1) { if (tid < s) red[tid] += red[tid+s]; __syncthreads(); }
    float mean = red[0] * (1.0f/256.0f);
    __syncthreads();
    float d = acc - mean;
    red[tid] = d*d; __syncthreads();
    #pragma unroll
    for (int s = 128; s > 0; s >>= 1) { if (tid < s) red[tid] += red[tid+s]; __syncthreads(); }
    float var = red[0] * (1.0f/256.0f);
    float z = d * rsqrtf(var + 1e-5f) * gam[o] + bet[o];
    float* Y = stage ? g_z1 : g_z0;
    Y[((size_t)b*128 + o)*NPT + p] = fmaxf(z, 0.0f);
}

__global__ void final_kernel(const float* __restrict__ W, const float* __restrict__ bias,
                             float* __restrict__ out)
{
    int b = blockIdx.x, p = threadIdx.x;
    const float* Z = g_z1 + (size_t)b*128*NPT;
    float acc = bias[0];
    #pragma unroll 8
    for (int c = 0; c < 128; c++) acc = fmaf(W[c], Z[(size_t)c*NPT + p], acc);
    out[b*NPT + p] = acc;
}

// ---------------- launch ----------------
extern "C" void kernel_launch(void* const* d_in, const int* in_sizes, int n_in,
                              void* d_out, int out_size)
{
    const float* oxyz  = (const float*)d_in[0];
    const float* ofeat = (const float*)d_in[1];
    const float* cand  = (const float*)d_in[2];
    // d_in[3] = pred_cls (unused)
    const float* poff  = (const float*)d_in[4];
    const float* pacls = (const float*)d_in[5];
    const float* pares = (const float*)d_in[6];
    const float* w1    = (const float*)d_in[7];
    const float* b1    = (const float*)d_in[8];
    const float* w2    = (const float*)d_in[9];
    const float* b2    = (const float*)d_in[10];
    const float* wi0   = (const float*)d_in[11];
    const float* bi0   = (const float*)d_in[12];
    const float* gi0   = (const float*)d_in[13];
    const float* bei0  = (const float*)d_in[14];
    const float* wi1   = (const float*)d_in[15];
    const float* bi1   = (const float*)d_in[16];
    const float* gi1   = (const float*)d_in[17];
    const float* bei1  = (const float*)d_in[18];
    const float* wi2   = (const float*)d_in[19];
    const float* bi2   = (const float*)d_in[20];
    float* out = (float*)d_out;

    setup_a_kernel<<<128, 256>>>(cand, poff, pacls, pares, oxyz);   // #1
    center3_kernel<<<32, 256>>>(oxyz);                              // #2
    compact_kernel<<<256, 256>>>(oxyz);                             // #3
    threenn_cand_kernel<<<512, 256>>>(oxyz);                        // #4 <- ncu lands here
    setup_b_kernel<<<192, 256>>>(w1, w2);                           // #5
    gemmG_kernel<<<dim3(64, 2, 2), 256>>>(ofeat);                   // #6
    combine_kernel<<<512, 256>>>(w1, b1);                           // #7
    gemm2_pool_kernel<<<dim3(128, 4), 256>>>(b2);                   // #8
    lin_bn_kernel<<<128, 256>>>(wi0, bi0, gi0, bei0, 0);            // #9
    lin_bn_kernel<<<128, 256>>>(wi1, bi1, gi1, bei1, 1);            // #10
    final_kernel<<<2, 128>>>(wi2, bi2, out);                        // #11
}

// round 13
// speedup vs baseline: 1.1448x; 1.1448x over previous
#include <cuda_runtime.h>
#include <math.h>
#include <stdint.h>

#define BS2   2
#define NN    8192
#define NPT   128
#define CC    128
#define M_TOT 8192        // NPT*64 per batch
#define MG    16384       // total corners
#define NBOX  256         // BS2*NPT
#define CAP   8192        // max candidates per box
#define NSEG  4
#define FULLM 0xffffffffu

// ---------------- device scratch ----------------
static __device__ float g_p2[(size_t)BS2*NN];
static __device__ float g_rel[(size_t)MG*3];
static __device__ float g_cor[(size_t)MG*3];
static __device__ int   g_nni[(size_t)MG*3];
static __device__ float g_nnw[(size_t)MG*3];
static __device__ float g_ctr[NBOX*3];
static __device__ float g_md[NBOX];
static __device__ float g_R2[NBOX];
static __device__ float4 g_cpts[(size_t)NBOX*CAP];
static __device__ int    g_cidx[(size_t)NBOX*CAP];
static __device__ int    g_ccnt[NBOX];
static __device__ float g_pd[(size_t)MG*NSEG*3];
static __device__ int   g_pi[(size_t)MG*NSEG*3];
static __device__ float g_w1T[128*128];                 // [k][o]
static __device__ float g_w2T[128*256];                 // [k][o]
static __device__ float g_G[(size_t)BS2*NN*128];        // [b][n][o] = W1f . f
static __device__ float g_h1T[(size_t)128*MG];          // [c][m]
static __device__ float g_pool[(size_t)BS2*256*NPT];    // [b][o][p]
static __device__ float g_z0[(size_t)BS2*128*NPT];
static __device__ float g_z1[(size_t)BS2*128*NPT];

__device__ __forceinline__ float tf32r(float x) {
    uint32_t u; asm("cvt.rna.tf32.f32 %0, %1;" : "=r"(u) : "f"(x));
    return __uint_as_float(u);
}

__device__ __forceinline__ void mma_tf32(float c[4], const uint32_t a[4], const uint32_t b[2]) {
    asm volatile(
        "mma.sync.aligned.m16n8k8.row.col.f32.tf32.tf32.f32 "
        "{%0,%1,%2,%3}, {%4,%5,%6,%7}, {%8,%9}, {%0,%1,%2,%3};\n"
        : "+f"(c[0]), "+f"(c[1]), "+f"(c[2]), "+f"(c[3])
        : "r"(a[0]), "r"(a[1]), "r"(a[2]), "r"(a[3]), "r"(b[0]), "r"(b[1]));
}

// ---------------- setup_a: decode + p2 + per-box center/halfdiag ----------------
__global__ void setup_a_kernel(const float* __restrict__ cand,
                               const float* __restrict__ off,
                               const float* __restrict__ acls,
                               const float* __restrict__ ares,
                               const float* __restrict__ oxyz)
{
    int bx = blockIdx.x, tid = threadIdx.x;
    if (bx < 64) {
        int t = bx*256 + tid;                        // 16384 = b*8192 + p*64 + k
        int k  = t & 63;
        int bp = t >> 6;
        const float* a = acls + bp*12;
        float best = a[0]; int bi = 0;
        #pragma unroll
        for (int j = 1; j < 12; j++) { float v = a[j]; if (v > best) { best = v; bi = j; } }
        float res = ares[bp*12 + bi];
        const float PI_F = 3.14159265358979323846f;
        float ang = (float)bi * (float)(2.0*3.14159265358979323846/12.0) + res;
        float heading = (ang > PI_F) ? (ang - 2.0f*PI_F) : ang;
        float s, c; sincosf(heading, &s, &c);
        const float* o6 = off + bp*6;
        float cx = cand[bp*3+0] + o6[0];
        float cy = cand[bp*3+1] + o6[1];
        float cz = cand[bp*3+2] + o6[2];
        float lx = fmaxf(o6[3]*2.0f, 0.1f);
        float ly = fmaxf(o6[4]*2.0f, 0.1f);
        float lz = fmaxf(o6[5]*2.0f, 0.1f);
        if (k == 0) {
            g_ctr[bp*3+0] = cx; g_ctr[bp*3+1] = cy; g_ctr[bp*3+2] = cz;
            g_md[bp] = sqrtf(lx*lx + ly*ly + lz*lz);
        }
        float gv[4] = {-1.0f, -1.0f/3.0f, 1.0f/3.0f, 1.0f};
        float gx = gv[(k>>4)&3] * lx;
        float gy = gv[(k>>2)&3] * ly;
        float gz = gv[k&3]      * lz;
        float rx = gx*c - gy*s;
        float ry = gx*s + gy*c;
        float rz = gz;
        size_t b3 = (size_t)t*3;
        g_rel[b3+0] = rx; g_rel[b3+1] = ry; g_rel[b3+2] = rz;
        g_cor[b3+0] = rx + cx; g_cor[b3+1] = ry + cy; g_cor[b3+2] = rz + cz;
    } else {
        int t = (bx-64)*256 + tid;
        float x = oxyz[t*3], y = oxyz[t*3+1], z = oxyz[t*3+2];
        g_p2[t] = x*x + y*y + z*z;
    }
}

// values-only top-3 insert
#define INSERT3V(tt, d0, d1, d2)                               \
    do {                                                        \
        bool q2 = (tt) < (d2), q1 = (tt) < (d1), q0 = (tt) < (d0); \
        (d2) = q1 ? (d1) : (q2 ? (tt) : (d2));                  \
        (d1) = q0 ? (d0) : (q1 ? (tt) : (d1));                  \
        (d0) = q0 ? (tt) : (d0);                                \
    } while (0)

// ---------------- center3: block per center, exact d3 -> pruning radius^2 ----------------
__global__ void __launch_bounds__(256) center3_kernel(const float* __restrict__ oxyz)
{
    __shared__ float s_d[24];
    int cid = blockIdx.x;                        // 0..255
    int b = cid >> 7;
    int tid = threadIdx.x, lane = tid & 31, wid = tid >> 5;
    const float* O = oxyz + (size_t)b*NN*3;
    const float* Q = g_p2 + (size_t)b*NN;
    float cx = g_ctr[cid*3+0], cy = g_ctr[cid*3+1], cz = g_ctr[cid*3+2];
    float c2 = cx*cx + cy*cy + cz*cz;
    float ax = -2.0f*cx, ay = -2.0f*cy, az = -2.0f*cz;
    float d0 = 1e30f, d1 = 1e30f, d2v = 1e30f;
    for (int n = wid*1024 + lane; n < (wid+1)*1024; n += 32) {
        float t = Q[n] + c2;
        t = fmaf(ax, O[n*3+0], t);
        t = fmaf(ay, O[n*3+1], t);
        t = fmaf(az, O[n*3+2], t);
        if (t < d2v) INSERT3V(t, d0, d1, d2v);
    }
    #pragma unroll
    for (int offi = 16; offi; offi >>= 1) {
        float e0 = __shfl_xor_sync(FULLM, d0, offi);
        float e1 = __shfl_xor_sync(FULLM, d1, offi);
        float e2 = __shfl_xor_sync(FULLM, d2v, offi);
        INSERT3V(e0, d0, d1, d2v);
        INSERT3V(e1, d0, d1, d2v);
        INSERT3V(e2, d0, d1, d2v);
    }
    if (lane == 0) { s_d[wid*3+0] = d0; s_d[wid*3+1] = d1; s_d[wid*3+2] = d2v; }
    __syncthreads();
    if (tid == 0) {
        float f0 = 1e30f, f1 = 1e30f, f2 = 1e30f;
        #pragma unroll
        for (int i = 0; i < 24; i++) INSERT3V(s_d[i], f0, f1, f2);
        float r = sqrtf(fmaxf(f2, 0.0f)) + 2.0f*g_md[cid] + 1e-2f;
        g_R2[cid] = r*r*1.0001f + 1e-3f;
    }
}

// ---------------- compact: per-box ordered candidate list ----------------
__global__ void __launch_bounds__(256) compact_kernel(const float* __restrict__ oxyz)
{
    __shared__ int s_warp[8];
    __shared__ int s_base;
    int box = blockIdx.x;                         // 0..255
    int b = box >> 7;
    int tid = threadIdx.x, lane = tid & 31, wid = tid >> 5;
    const float* O = oxyz + (size_t)b*NN*3;
    const float* Q = g_p2 + (size_t)b*NN;
    float cx = g_ctr[box*3+0], cy = g_ctr[box*3+1], cz = g_ctr[box*3+2];
    float c2 = cx*cx + cy*cy + cz*cz;
    float ax = -2.0f*cx, ay = -2.0f*cy, az = -2.0f*cz;
    float R2 = g_R2[box];
    float4* CP = g_cpts + (size_t)box*CAP;
    int*    CI = g_cidx + (size_t)box*CAP;
    if (tid == 0) s_base = 0;
    __syncthreads();
    for (int t0 = 0; t0 < NN; t0 += 256) {
        int n = t0 + tid;
        float x = O[n*3+0], y = O[n*3+1], z = O[n*3+2];
        float p2 = Q[n];
        float d = p2 + c2;
        d = fmaf(ax, x, d); d = fmaf(ay, y, d); d = fmaf(az, z, d);
        bool keep = d <= R2;
        unsigned mask = __ballot_sync(FULLM, keep);
        if (lane == 0) s_warp[wid] = __popc(mask);
        __syncthreads();
        int prev = 0, tot = 0;
        #pragma unroll
        for (int w = 0; w < 8; w++) {
            int cn = s_warp[w];
            if (w < wid) prev += cn;
            tot += cn;
        }
        int pos = s_base + prev + __popc(mask & ((1u << lane) - 1u));
        if (keep) {
            CP[pos] = make_float4(x, y, z, p2);
            CI[pos] = n;
        }
        __syncthreads();
        if (tid == 0) s_base += tot;
        __syncthreads();
    }
    if (tid == 0) g_ccnt[box] = s_base;
}

// warp-uniform insert with index
#define INSERT3(tt, nn_, d0, i0, d1, i1, d2, i2)               \
    do {                                                        \
        bool q2 = (tt) < (d2), q1 = (tt) < (d1), q0 = (tt) < (d0); \
        (d2) = q1 ? (d1) : (q2 ? (tt) : (d2));                  \
        (i2) = q1 ? (i1) : (q2 ? (nn_) : (i2));                 \
        (d1) = q0 ? (d0) : (q1 ? (tt) : (d1));                  \
        (i1) = q0 ? (i0) : (q1 ? (nn_) : (i1));                 \
        (d0) = q0 ? (tt) : (d0);                                \
        (i0) = q0 ? (nn_) : (i0);                               \
    } while (0)

#define DRAIN(bal, tval, d0, i0, d1, i1, d2, i2, nbase)        \
    while (bal) {                                               \
        int s = __ffs(bal) - 1; bal &= bal - 1;                 \
        float tt = __shfl_sync(FULLM, tval, s);                 \
        int nn_ = (nbase) + s;                                  \
        INSERT3(tt, nn_, d0, i0, d1, i1, d2, i2);               \
    }

// ---------------- stage D: partial top-3 per (corner, segment), prefetched ----------------
__global__ void __launch_bounds__(256) threenn_part_kernel()
{
    int tid = threadIdx.x, lane = tid & 31, wid = tid >> 5;
    int box = blockIdx.x >> 1;                    // 2 blocks per box (x)
    int seg = blockIdx.y;                         // 0..3
    int b = box >> 7, p = box & 127;
    int g = (blockIdx.x & 1)*8 + wid;             // corner group 0..15
    int k0 = g*4;
    int mg = b*M_TOT + p*64 + k0;                 // global corner of A
    size_t cb = (size_t)mg*3;

    float c2A, axA, ayA, azA, c2B, axB, ayB, azB;
    float c2C, axC, ayC, azC, c2D, axD, ayD, azD;
    {
        float x, y, z;
        x = g_cor[cb+0];  y = g_cor[cb+1];  z = g_cor[cb+2];
        c2A = x*x+y*y+z*z; axA = -2.0f*x; ayA = -2.0f*y; azA = -2.0f*z;
        x = g_cor[cb+3];  y = g_cor[cb+4];  z = g_cor[cb+5];
        c2B = x*x+y*y+z*z; axB = -2.0f*x; ayB = -2.0f*y; azB = -2.0f*z;
        x = g_cor[cb+6];  y = g_cor[cb+7];  z = g_cor[cb+8];
        c2C = x*x+y*y+z*z; axC = -2.0f*x; ayC = -2.0f*y; azC = -2.0f*z;
        x = g_cor[cb+9];  y = g_cor[cb+10]; z = g_cor[cb+11];
        c2D = x*x+y*y+z*z; axD = -2.0f*x; ayD = -2.0f*y; azD = -2.0f*z;
    }

    int cnt = g_ccnt[box];
    int per = (cnt + NSEG - 1) / NSEG;
    int s0 = seg*per;
    int s1 = min(s0 + per, cnt);
    const float4* CP = g_cpts + (size_t)box*CAP;
    const int*    CI = g_cidx + (size_t)box*CAP;

    float dA0=1e30f,dA1=1e30f,dA2=1e30f; int iA0=0,iA1=0,iA2=0;
    float dB0=1e30f,dB1=1e30f,dB2=1e30f; int iB0=0,iB1=0,iB2=0;
    float dC0=1e30f,dC1=1e30f,dC2=1e30f; int iC0=0,iC1=0,iC2=0;
    float dD0=1e30f,dD1=1e30f,dD2=1e30f; int iD0=0,iD1=0,iD2=0;

    if (s0 < s1) {
        int pos0 = s0 + lane;
        float4 pt = CP[min(pos0, cnt-1)];
        if (pos0 >= s1) pt.w = 1e30f;
        for (int base = s0; base < s1; base += 32) {
            float4 cur = pt;
            int nbase2 = base + 32;
            if (nbase2 < s1) {
                int np = nbase2 + lane;
                pt = CP[min(np, cnt-1)];
                if (np >= s1) pt.w = 1e30f;
            }
            float tA = fmaf(axA, cur.x, cur.w + c2A); tA = fmaf(ayA, cur.y, tA); tA = fmaf(azA, cur.z, tA);
            float tB = fmaf(axB, cur.x, cur.w + c2B); tB = fmaf(ayB, cur.y, tB); tB = fmaf(azB, cur.z, tB);
            float tC = fmaf(axC, cur.x, cur.w + c2C); tC = fmaf(ayC, cur.y, tC); tC = fmaf(azC, cur.z, tC);
            float tD = fmaf(axD, cur.x, cur.w + c2D); tD = fmaf(ayD, cur.y, tD); tD = fmaf(azD, cur.z, tD);
            bool hit = (tA < dA2) | (tB < dB2) | (tC < dC2) | (tD < dD2);
            if (__any_sync(FULLM, hit)) {
                unsigned bal;
                bal = __ballot_sync(FULLM, tA < dA2); DRAIN(bal, tA, dA0, iA0, dA1, iA1, dA2, iA2, base);
                bal = __ballot_sync(FULLM, tB < dB2); DRAIN(bal, tB, dB0, iB0, dB1, iB1, dB2, iB2, base);
                bal = __ballot_sync(FULLM, tC < dC2); DRAIN(bal, tC, dC0, iC0, dC1, iC1, dC2, iC2, base);
                bal = __ballot_sync(FULLM, tD < dD2); DRAIN(bal, tD, dD0, iD0, dD1, iD1, dD2, iD2, base);
            }
        }
    }
    if (lane == 0) {
        size_t pb = ((size_t)mg*NSEG + seg)*3;
        g_pd[pb+0] = dA0; g_pd[pb+1] = dA1; g_pd[pb+2] = dA2;
        g_pi[pb+0] = (dA0 < 1e30f) ? CI[iA0] : 0;
        g_pi[pb+1] = (dA1 < 1e30f) ? CI[iA1] : 0;
        g_pi[pb+2] = (dA2 < 1e30f) ? CI[iA2] : 0;
        pb += (size_t)NSEG*3;
        g_pd[pb+0] = dB0; g_pd[pb+1] = dB1; g_pd[pb+2] = dB2;
        g_pi[pb+0] = (dB0 < 1e30f) ? CI[iB0] : 0;
        g_pi[pb+1] = (dB1 < 1e30f) ? CI[iB1] : 0;
        g_pi[pb+2] = (dB2 < 1e30f) ? CI[iB2] : 0;
        pb += (size_t)NSEG*3;
        g_pd[pb+0] = dC0; g_pd[pb+1] = dC1; g_pd[pb+2] = dC2;
        g_pi[pb+0] = (dC0 < 1e30f) ? CI[iC0] : 0;
        g_pi[pb+1] = (dC1 < 1e30f) ? CI[iC1] : 0;
        g_pi[pb+2] = (dC2 < 1e30f) ? CI[iC2] : 0;
        pb += (size_t)NSEG*3;
        g_pd[pb+0] = dD0; g_pd[pb+1] = dD1; g_pd[pb+2] = dD2;
        g_pi[pb+0] = (dD0 < 1e30f) ? CI[iD0] : 0;
        g_pi[pb+1] = (dD1 < 1e30f) ? CI[iD1] : 0;
        g_pi[pb+2] = (dD2 < 1e30f) ? CI[iD2] : 0;
    }
}

// ---------------- merge: combine 4 segment partials per corner, write weights ----------------
__global__ void __launch_bounds__(256) merge_kernel(const float* __restrict__ oxyz)
{
    int mg = blockIdx.x*256 + threadIdx.x;        // 0..16383
    int b = mg >> 13;
    const float* O = oxyz + (size_t)b*NN*3;
    size_t pb = (size_t)mg*NSEG*3;
    float d0 = 1e30f, d1 = 1e30f, d2 = 1e30f;
    int i0 = 0, i1 = 0, i2 = 0;
    #pragma unroll
    for (int s = 0; s < NSEG*3; s++) {
        float dv = g_pd[pb + s];
        int   iv = g_pi[pb + s];
        INSERT3(dv, iv, d0, i0, d1, i1, d2, i2);
    }
    size_t cb = (size_t)mg*3;
    float cx = g_cor[cb+0], cy = g_cor[cb+1], cz = g_cor[cb+2];
    int win[3] = {i0, i1, i2};
    float w[3], ssum = 0.0f;
    #pragma unroll
    for (int r = 0; r < 3; r++) {
        const float* P = O + (size_t)win[r]*3;
        float dx = P[0]-cx, dy = P[1]-cy, dz = P[2]-cz;
        float d = sqrtf(dx*dx + dy*dy + dz*dz);
        w[r] = 1.0f / (d + 1e-8f);
        ssum += w[r];
    }
    float inv = 1.0f/ssum;
    #pragma unroll
    for (int r = 0; r < 3; r++) { g_nni[cb+r] = win[r]; g_nnw[cb+r] = w[r]*inv; }
}

// ---------------- setup_b: transpose W1f / W2 ----------------
__global__ void setup_b_kernel(const float* __restrict__ w1, const float* __restrict__ w2)
{
    int bx = blockIdx.x, tid = threadIdx.x;
    if (bx < 64) {
        int t = bx*256 + tid;                        // 16384 = k*128+o
        int o = t & 127, k = t >> 7;
        g_w1T[t] = w1[o*131 + 3 + k];
    } else {
        int t = (bx-64)*256 + tid;                   // 32768 = k*256+o
        int o = t & 255, k = t >> 8;
        g_w2T[t] = w2[o*128 + k];
    }
}

// ---------------- gemm_G: 128n x 64o, BK=16, 8x4, double-buffered (proven) ----------------
__global__ void __launch_bounds__(256) gemmG_kernel(const float* __restrict__ feat)
{
    __shared__ float Ns[2][16][132];
    __shared__ float Os[2][16][64];
    int n0 = blockIdx.x*128, o0 = blockIdx.y*64, b = blockIdx.z;
    int tid = threadIdx.x;
    int kr  = tid >> 4;
    int nc  = (tid & 15)*8;
    int oc  = (tid & 15)*4;
    int tr  = (tid >> 4)*8;
    int tc  = (tid & 15)*4;
    const float* F = feat + (size_t)b*CC*NN;

    float acc[8][4] = {};
    float4 na0, na1, nb;
    na0 = *(const float4*)&F[(size_t)kr*NN + n0 + nc];
    na1 = *(const float4*)&F[(size_t)kr*NN + n0 + nc + 4];
    nb  = *(const float4*)&g_w1T[kr*128 + o0 + oc];
    *(float4*)&Ns[0][kr][nc]   = na0;
    *(float4*)&Ns[0][kr][nc+4] = na1;
    *(float4*)&Os[0][kr][oc]   = nb;
    __syncthreads();
    int buf = 0;
    #pragma unroll 1
    for (int kb = 0; kb < 8; kb++) {
        bool has = kb < 7;
        if (has) {
            int kk = (kb+1)*16 + kr;
            na0 = *(const float4*)&F[(size_t)kk*NN + n0 + nc];
            na1 = *(const float4*)&F[(size_t)kk*NN + n0 + nc + 4];
            nb  = *(const float4*)&g_w1T[kk*128 + o0 + oc];
        }
        #pragma unroll
        for (int k = 0; k < 16; k++) {
            float4 a0 = *(const float4*)&Ns[buf][k][tr];
            float4 a1 = *(const float4*)&Ns[buf][k][tr+4];
            float4 bq = *(const float4*)&Os[buf][k][tc];
            float ar[8] = {a0.x,a0.y,a0.z,a0.w,a1.x,a1.y,a1.z,a1.w};
            float br[4] = {bq.x,bq.y,bq.z,bq.w};
            #pragma unroll
            for (int i = 0; i < 8; i++)
                #pragma unroll
                for (int j = 0; j < 4; j++)
                    acc[i][j] = fmaf(ar[i], br[j], acc[i][j]);
        }
        if (has) {
            int nbuf = buf^1;
            *(float4*)&Ns[nbuf][kr][nc]   = na0;
            *(float4*)&Ns[nbuf][kr][nc+4] = na1;
            *(float4*)&Os[nbuf][kr][oc]   = nb;
            __syncthreads();
            buf = nbuf;
        }
    }
    float* Gp = g_G + ((size_t)b*NN + n0 + tr)*128 + o0 + tc;
    #pragma unroll
    for (int i = 0; i < 8; i++) {
        float4 v = {acc[i][0], acc[i][1], acc[i][2], acc[i][3]};
        *(float4*)(Gp + (size_t)i*128) = v;
    }
}

// ---------------- combine v2: block = 32 corners, coalesced h1T row writes ----------------
__global__ void __launch_bounds__(256) combine_kernel(const float* __restrict__ w1,
                                                      const float* __restrict__ b1)
{
    __shared__ float wr0[128], wr1[128], wr2[128], sb[128];
    __shared__ float tr[128][33];
    int tid = threadIdx.x, lane = tid & 31, wid = tid >> 5;
    if (tid < 128) {
        const float* wrow = w1 + tid*131;
        wr0[tid] = wrow[0]; wr1[tid] = wrow[1]; wr2[tid] = wrow[2];
        sb[tid]  = b1[tid];
    }
    __syncthreads();
    int m0 = blockIdx.x*32;
    #pragma unroll 1
    for (int cc = 0; cc < 4; cc++) {
        int ml = wid*4 + cc;                         // 0..31 local corner
        int m  = m0 + ml;
        int b = m >> 13, mb = m & 8191;
        size_t base3 = ((size_t)b*M_TOT + mb)*3;
        int i0 = g_nni[base3+0], i1 = g_nni[base3+1], i2 = g_nni[base3+2];
        float w0 = g_nnw[base3+0], w1w = g_nnw[base3+1], w2w = g_nnw[base3+2];
        float rx = g_rel[(size_t)m*3+0], ry = g_rel[(size_t)m*3+1], rz = g_rel[(size_t)m*3+2];
        const float* G0 = g_G + ((size_t)b*NN + i0)*128;
        const float* G1 = g_G + ((size_t)b*NN + i1)*128;
        const float* G2 = g_G + ((size_t)b*NN + i2)*128;
        int c0 = lane*4;
        float4 a  = *(const float4*)(G0 + c0);
        float4 bq = *(const float4*)(G1 + c0);
        float4 cq = *(const float4*)(G2 + c0);
        float va[4] = {a.x,a.y,a.z,a.w};
        float vb[4] = {bq.x,bq.y,bq.z,bq.w};
        float vc[4] = {cq.x,cq.y,cq.z,cq.w};
        #pragma unroll
        for (int j = 0; j < 4; j++) {
            int o = c0 + j;
            float acc = w0*va[j] + w1w*vb[j] + w2w*vc[j];
            acc = fmaf(rx, wr0[o], acc);
            acc = fmaf(ry, wr1[o], acc);
            acc = fmaf(rz, wr2[o], acc);
            tr[o][ml] = fmaxf(acc + sb[o], 0.0f);
        }
    }
    __syncthreads();
    int c = tid >> 1, base = (tid & 1)*16;
    float* dst = &g_h1T[(size_t)c*MG + m0 + base];
    #pragma unroll
    for (int q = 0; q < 4; q++) {
        float4 v = {tr[c][base+q*4+0], tr[c][base+q*4+1], tr[c][base+q*4+2], tr[c][base+q*4+3]};
        *(float4*)(dst + q*4) = v;
    }
}

// ---------------- gemm2 (tf32 tensor-core) + fused relu + maxpool over 64 ----------------
__global__ void __launch_bounds__(256) gemm2_pool_kernel(const float* __restrict__ bias)
{
    __shared__ float As[2][16][132];     // [k][m], padded
    __shared__ float Bs[2][16][68];      // [k][o], padded
    __shared__ int spool[128];           // [2 pool-groups][64 o]
    int m0 = blockIdx.x*128, o0 = blockIdx.y*64;
    int tid = threadIdx.x, lane = tid & 31, wid = tid >> 5;
    int wm = wid >> 1, wn = wid & 1;
    int kr = tid >> 4, c16 = tid & 15;
    if (tid < 128) spool[tid] = 0;

    float acc[2][4][4] = {};

    {
        const float* ap = &g_h1T[(size_t)kr*MG + m0 + c16*8];
        float4 a0 = *(const float4*)ap;
        float4 a1 = *(const float4*)(ap + 4);
        float* d = &As[0][kr][c16*8];
        d[0]=tf32r(a0.x); d[1]=tf32r(a0.y); d[2]=tf32r(a0.z); d[3]=tf32r(a0.w);
        d[4]=tf32r(a1.x); d[5]=tf32r(a1.y); d[6]=tf32r(a1.z); d[7]=tf32r(a1.w);
        float4 bv = *(const float4*)&g_w2T[kr*256 + o0 + c16*4];
        float* e = &Bs[0][kr][c16*4];
        e[0]=tf32r(bv.x); e[1]=tf32r(bv.y); e[2]=tf32r(bv.z); e[3]=tf32r(bv.w);
    }
    __syncthreads();

    int buf = 0;
    int lk = lane & 3, lr = lane >> 2;
    #pragma unroll 1
    for (int kb = 0; kb < 8; kb++) {
        bool has = kb < 7;
        float4 na0, na1, nb;
        if (has) {
            int kk = (kb+1)*16 + kr;
            const float* ap = &g_h1T[(size_t)kk*MG + m0 + c16*8];
            na0 = *(const float4*)ap;
            na1 = *(const float4*)(ap + 4);
            nb  = *(const float4*)&g_w2T[kk*256 + o0 + c16*4];
        }
        #pragma unroll
        for (int ks = 0; ks < 2; ks++) {
            int klo = ks*8 + lk;
            uint32_t afr[2][4];
            #pragma unroll
            for (int mt = 0; mt < 2; mt++) {
                int mr = wm*32 + mt*16 + lr;
                afr[mt][0] = __float_as_uint(As[buf][klo  ][mr]);
                afr[mt][1] = __float_as_uint(As[buf][klo  ][mr+8]);
                afr[mt][2] = __float_as_uint(As[buf][klo+4][mr]);
                afr[mt][3] = __float_as_uint(As[buf][klo+4][mr+8]);
            }
            uint32_t bfr[4][2];
            #pragma unroll
            for (int nt = 0; nt < 4; nt++) {
                int nr = wn*32 + nt*8 + lr;
                bfr[nt][0] = __float_as_uint(Bs[buf][klo  ][nr]);
                bfr[nt][1] = __float_as_uint(Bs[buf][klo+4][nr]);
            }
            #pragma unroll
            for (int mt = 0; mt < 2; mt++)
                #pragma unroll
                for (int nt = 0; nt < 4; nt++)
                    mma_tf32(acc[mt][nt], afr[mt], bfr[nt]);
        }
        if (has) {
            int nbuf = buf^1;
            float* d = &As[nbuf][kr][c16*8];
            d[0]=tf32r(na0.x); d[1]=tf32r(na0.y); d[2]=tf32r(na0.z); d[3]=tf32r(na0.w);
            d[4]=tf32r(na1.x); d[5]=tf32r(na1.y); d[6]=tf32r(na1.z); d[7]=tf32r(na1.w);
            float* e = &Bs[nbuf][kr][c16*4];
            e[0]=tf32r(nb.x); e[1]=tf32r(nb.y); e[2]=tf32r(nb.z); e[3]=tf32r(nb.w);
            __syncthreads();
            buf = nbuf;
        }
    }

    int grp = wm >> 1;
    #pragma unroll
    for (int nt = 0; nt < 4; nt++) {
        int c0 = wn*32 + nt*8 + (lane & 3)*2;
        float b0v = bias[o0 + c0], b1v = bias[o0 + c0 + 1];
        float p0v = 0.0f, p1v = 0.0f;
        #pragma unroll
        for (int mt = 0; mt < 2; mt++) {
            p0v = fmaxf(p0v, acc[mt][nt][0] + b0v);
            p0v = fmaxf(p0v, acc[mt][nt][2] + b0v);
            p1v = fmaxf(p1v, acc[mt][nt][1] + b1v);
            p1v = fmaxf(p1v, acc[mt][nt][3] + b1v);
        }
        atomicMax(&spool[grp*64 + c0],     __float_as_int(p0v));
        atomicMax(&spool[grp*64 + c0 + 1], __float_as_int(p1v));
    }
    __syncthreads();
    if (tid < 128) {
        int g = tid >> 6, ol = tid & 63;
        int b  = m0 >> 13;
        int p0 = (m0 >> 6) & 127;
        g_pool[((size_t)b*256 + o0 + ol)*NPT + p0 + g] = __int_as_float(spool[g*64 + ol]);
    }
}

// ---------------- fused linear + train-mode BN + relu ----------------
__global__ void lin_bn_kernel(const float* __restrict__ W, const float* __restrict__ bias,
                              const float* __restrict__ gam, const float* __restrict__ bet,
                              int stage)
{
    int o = blockIdx.x, tid = threadIdx.x;            // 256 threads = (b,p)
    int b = tid >> 7, p = tid & 127;
    int K = stage ? 128 : 256;
    const float* X = stage ? g_z0 : g_pool;
    __shared__ float ws[256];
    if (tid < K) ws[tid] = W[o*K + tid];
    __syncthreads();
    const float* Xb = X + (size_t)b*K*NPT + p;
    float acc = bias[o];
    #pragma unroll 8
    for (int c = 0; c < K; c++) acc = fmaf(ws[c], Xb[(size_t)c*NPT], acc);
    __shared__ float red[256];
    red[tid] = acc; __syncthreads();
    #pragma unroll
    for (int s = 128; s > 0; s >>= 1) { if (tid < s) red[tid] += red[tid+s]; __syncthreads(); }
    float mean = red[0] * (1.0f/256.0f);
    __syncthreads();
    float d = acc - mean;
    red[tid] = d*d; __syncthreads();
    #pragma unroll
    for (int s = 128; s > 0; s >>= 1) { if (tid < s) red[tid] += red[tid+s]; __syncthreads(); }
    float var = red[0] * (1.0f/256.0f);
    float z = d * rsqrtf(var + 1e-5f) * gam[o] + bet[o];
    float* Y = stage ? g_z1 : g_z0;
    Y[((size_t)b*128 + o)*NPT + p] = fmaxf(z, 0.0f);
}

__global__ void final_kernel(const float* __restrict__ W, const float* __restrict__ bias,
                             float* __restrict__ out)
{
    int b = blockIdx.x, p = threadIdx.x;
    const float* Z = g_z1 + (size_t)b*128*NPT;
    float acc = bias[0];
    #pragma unroll 8
    for (int c = 0; c < 128; c++) acc = fmaf(W[c], Z[(size_t)c*NPT + p], acc);
    out[b*NPT + p] = acc;
}

// ---------------- launch ----------------
extern "C" void kernel_launch(void* const* d_in, const int* in_sizes, int n_in,
                              void* d_out, int out_size)
{
    const float* oxyz  = (const float*)d_in[0];
    const float* ofeat = (const float*)d_in[1];
    const float* cand  = (const float*)d_in[2];
    // d_in[3] = pred_cls (unused)
    const float* poff  = (const float*)d_in[4];
    const float* pacls = (const float*)d_in[5];
    const float* pares = (const float*)d_in[6];
    const float* w1    = (const float*)d_in[7];
    const float* b1    = (const float*)d_in[8];
    const float* w2    = (const float*)d_in[9];
    const float* b2    = (const float*)d_in[10];
    const float* wi0   = (const float*)d_in[11];
    const float* bi0   = (const float*)d_in[12];
    const float* gi0   = (const float*)d_in[13];
    const float* bei0  = (const float*)d_in[14];
    const float* wi1   = (const float*)d_in[15];
    const float* bi1   = (const float*)d_in[16];
    const float* gi1   = (const float*)d_in[17];
    const float* bei1  = (const float*)d_in[18];
    const float* wi2   = (const float*)d_in[19];
    const float* bi2   = (const float*)d_in[20];
    float* out = (float*)d_out;

    setup_a_kernel<<<128, 256>>>(cand, poff, pacls, pares, oxyz);   // #1
    center3_kernel<<<256, 256>>>(oxyz);                             // #2
    compact_kernel<<<256, 256>>>(oxyz);                             // #3
    threenn_part_kernel<<<dim3(512, NSEG), 256>>>();                // #4 <- ncu lands here
    merge_kernel<<<64, 256>>>(oxyz);                                // #5
    setup_b_kernel<<<192, 256>>>(w1, w2);                           // #6
    gemmG_kernel<<<dim3(64, 2, 2), 256>>>(ofeat);                   // #7
    combine_kernel<<<512, 256>>>(w1, b1);                           // #8
    gemm2_pool_kernel<<<dim3(128, 4), 256>>>(b2);                   // #9
    lin_bn_kernel<<<128, 256>>>(wi0, bi0, gi0, bei0, 0);            // #10
    lin_bn_kernel<<<128, 256>>>(wi1, bi1, gi1, bei1, 1);            // #11
    final_kernel<<<2, 128>>>(wi2, bi2, out);                        // #12
}

// round 14
// speedup vs baseline: 1.4096x; 1.2313x over previous
#include <cuda_runtime.h>
#include <math.h>
#include <stdint.h>

#define BS2   2
#define NN    8192
#define NPT   128
#define CC    128
#define M_TOT 8192        // NPT*64 per batch
#define MG    16384       // total corners
#define NBOX  256         // BS2*NPT
#define CAP   8192        // max candidates per box
#define NSEG  4
#define FULLM 0xffffffffu

// ---------------- device scratch ----------------
static __device__ float g_p2[(size_t)BS2*NN];
static __device__ float g_rel[(size_t)MG*3];
static __device__ float g_cor[(size_t)MG*3];
static __device__ int   g_nni[(size_t)MG*3];
static __device__ float g_nnw[(size_t)MG*3];
static __device__ float g_ctr[NBOX*3];
static __device__ float g_md[NBOX];
static __device__ float g_B2[NBOX];
static __device__ float4 g_cpts[(size_t)NBOX*CAP];
static __device__ int    g_cidx[(size_t)NBOX*CAP];
static __device__ int    g_ccnt[NBOX];
static __device__ float g_pd[(size_t)MG*NSEG*3];
static __device__ int   g_pi[(size_t)MG*NSEG*3];
static __device__ float g_w1T[128*128];                 // [k][o]
static __device__ float g_w2T[128*256];                 // [k][o]
static __device__ float g_G[(size_t)BS2*NN*128];        // [b][n][o] = W1f . f
static __device__ float g_h1T[(size_t)128*MG];          // [c][m]
static __device__ float g_pool[(size_t)BS2*256*NPT];    // [b][o][p]
static __device__ float g_z0[(size_t)BS2*128*NPT];
static __device__ float g_z1[(size_t)BS2*128*NPT];

__device__ __forceinline__ float tf32r(float x) {
    uint32_t u; asm("cvt.rna.tf32.f32 %0, %1;" : "=r"(u) : "f"(x));
    return __uint_as_float(u);
}

__device__ __forceinline__ void mma_tf32(float c[4], const uint32_t a[4], const uint32_t b[2]) {
    asm volatile(
        "mma.sync.aligned.m16n8k8.row.col.f32.tf32.tf32.f32 "
        "{%0,%1,%2,%3}, {%4,%5,%6,%7}, {%8,%9}, {%0,%1,%2,%3};\n"
        : "+f"(c[0]), "+f"(c[1]), "+f"(c[2]), "+f"(c[3])
        : "r"(a[0]), "r"(a[1]), "r"(a[2]), "r"(a[3]), "r"(b[0]), "r"(b[1]));
}

// ---------------- setup: decode + p2 + box meta + weight transposes ----------------
__global__ void setup_kernel(const float* __restrict__ cand,
                             const float* __restrict__ off,
                             const float* __restrict__ acls,
                             const float* __restrict__ ares,
                             const float* __restrict__ oxyz,
                             const float* __restrict__ w1,
                             const float* __restrict__ w2)
{
    int bx = blockIdx.x, tid = threadIdx.x;
    if (bx < 64) {
        int t = bx*256 + tid;                        // 16384 = b*8192 + p*64 + k
        int k  = t & 63;
        int bp = t >> 6;
        const float* a = acls + bp*12;
        float best = a[0]; int bi = 0;
        #pragma unroll
        for (int j = 1; j < 12; j++) { float v = a[j]; if (v > best) { best = v; bi = j; } }
        float res = ares[bp*12 + bi];
        const float PI_F = 3.14159265358979323846f;
        float ang = (float)bi * (float)(2.0*3.14159265358979323846/12.0) + res;
        float heading = (ang > PI_F) ? (ang - 2.0f*PI_F) : ang;
        float s, c; sincosf(heading, &s, &c);
        const float* o6 = off + bp*6;
        float cx = cand[bp*3+0] + o6[0];
        float cy = cand[bp*3+1] + o6[1];
        float cz = cand[bp*3+2] + o6[2];
        float lx = fmaxf(o6[3]*2.0f, 0.1f);
        float ly = fmaxf(o6[4]*2.0f, 0.1f);
        float lz = fmaxf(o6[5]*2.0f, 0.1f);
        if (k == 0) {
            g_ctr[bp*3+0] = cx; g_ctr[bp*3+1] = cy; g_ctr[bp*3+2] = cz;
            g_md[bp] = sqrtf(lx*lx + ly*ly + lz*lz);
        }
        float gv[4] = {-1.0f, -1.0f/3.0f, 1.0f/3.0f, 1.0f};
        float gx = gv[(k>>4)&3] * lx;
        float gy = gv[(k>>2)&3] * ly;
        float gz = gv[k&3]      * lz;
        float rx = gx*c - gy*s;
        float ry = gx*s + gy*c;
        float rz = gz;
        size_t b3 = (size_t)t*3;
        g_rel[b3+0] = rx; g_rel[b3+1] = ry; g_rel[b3+2] = rz;
        g_cor[b3+0] = rx + cx; g_cor[b3+1] = ry + cy; g_cor[b3+2] = rz + cz;
    } else if (bx < 128) {
        int t = (bx-64)*256 + tid;
        float x = oxyz[t*3], y = oxyz[t*3+1], z = oxyz[t*3+2];
        g_p2[t] = x*x + y*y + z*z;
    } else if (bx < 192) {
        int t = (bx-128)*256 + tid;                  // 16384 = k*128+o
        int o = t & 127, k = t >> 7;
        g_w1T[t] = w1[o*131 + 3 + k];
    } else {
        int t = (bx-192)*256 + tid;                  // 32768 = k*256+o
        int o = t & 255, k = t >> 8;
        g_w2T[t] = w2[o*128 + k];
    }
}

// values-only top-3 insert
#define INSERT3V(tt, d0, d1, d2)                               \
    do {                                                        \
        bool q2 = (tt) < (d2), q1 = (tt) < (d1), q0 = (tt) < (d0); \
        (d2) = q1 ? (d1) : (q2 ? (tt) : (d2));                  \
        (d1) = q0 ? (d0) : (q1 ? (tt) : (d1));                  \
        (d0) = q0 ? (tt) : (d0);                                \
    } while (0)

// ---------------- prune: per-box center-d3 then compaction (fused) ----------------
__global__ void __launch_bounds__(256) prune_kernel(const float* __restrict__ oxyz)
{
    __shared__ float s_d[24];
    __shared__ float s_R2;
    __shared__ int s_warp[8];
    __shared__ int s_base;
    int box = blockIdx.x;                         // 0..255
    int b = box >> 7;
    int tid = threadIdx.x, lane = tid & 31, wid = tid >> 5;
    const float* O = oxyz + (size_t)b*NN*3;
    const float* Q = g_p2 + (size_t)b*NN;
    float cx = g_ctr[box*3+0], cy = g_ctr[box*3+1], cz = g_ctr[box*3+2];
    float c2 = cx*cx + cy*cy + cz*cz;
    float ax = -2.0f*cx, ay = -2.0f*cy, az = -2.0f*cz;

    // phase 1: exact center d3
    float d0 = 1e30f, d1 = 1e30f, d2v = 1e30f;
    for (int n = wid*1024 + lane; n < (wid+1)*1024; n += 32) {
        float t = Q[n] + c2;
        t = fmaf(ax, O[n*3+0], t);
        t = fmaf(ay, O[n*3+1], t);
        t = fmaf(az, O[n*3+2], t);
        if (t < d2v) INSERT3V(t, d0, d1, d2v);
    }
    #pragma unroll
    for (int offi = 16; offi; offi >>= 1) {
        float e0 = __shfl_xor_sync(FULLM, d0, offi);
        float e1 = __shfl_xor_sync(FULLM, d1, offi);
        float e2 = __shfl_xor_sync(FULLM, d2v, offi);
        INSERT3V(e0, d0, d1, d2v);
        INSERT3V(e1, d0, d1, d2v);
        INSERT3V(e2, d0, d1, d2v);
    }
    if (lane == 0) { s_d[wid*3+0] = d0; s_d[wid*3+1] = d1; s_d[wid*3+2] = d2v; }
    if (tid == 0) s_base = 0;
    __syncthreads();
    if (tid == 0) {
        float f0 = 1e30f, f1 = 1e30f, f2 = 1e30f;
        #pragma unroll
        for (int i = 0; i < 24; i++) INSERT3V(s_d[i], f0, f1, f2);
        float d3 = sqrtf(fmaxf(f2, 0.0f));
        float md = g_md[box];
        float r = d3 + 2.0f*md + 1e-2f;
        s_R2 = r*r*1.0001f + 1e-3f;
        float bb = d3 + md + 1e-2f;
        g_B2[box] = bb*bb*1.0001f + 1e-3f;
    }
    __syncthreads();
    float R2 = s_R2;

    // phase 2: ordered compaction
    float4* CP = g_cpts + (size_t)box*CAP;
    int*    CI = g_cidx + (size_t)box*CAP;
    for (int t0 = 0; t0 < NN; t0 += 256) {
        int n = t0 + tid;
        float x = O[n*3+0], y = O[n*3+1], z = O[n*3+2];
        float p2 = Q[n];
        float d = p2 + c2;
        d = fmaf(ax, x, d); d = fmaf(ay, y, d); d = fmaf(az, z, d);
        bool keep = d <= R2;
        unsigned mask = __ballot_sync(FULLM, keep);
        if (lane == 0) s_warp[wid] = __popc(mask);
        __syncthreads();
        int prev = 0, tot = 0;
        #pragma unroll
        for (int w = 0; w < 8; w++) {
            int cn = s_warp[w];
            if (w < wid) prev += cn;
            tot += cn;
        }
        int pos = s_base + prev + __popc(mask & ((1u << lane) - 1u));
        if (keep) {
            CP[pos] = make_float4(x, y, z, p2);
            CI[pos] = n;
        }
        __syncthreads();
        if (tid == 0) s_base += tot;
        __syncthreads();
    }
    if (tid == 0) g_ccnt[box] = s_base;
}

// warp-uniform insert with index
#define INSERT3(tt, nn_, d0, i0, d1, i1, d2, i2)               \
    do {                                                        \
        bool q2 = (tt) < (d2), q1 = (tt) < (d1), q0 = (tt) < (d0); \
        (d2) = q1 ? (d1) : (q2 ? (tt) : (d2));                  \
        (i2) = q1 ? (i1) : (q2 ? (nn_) : (i2));                 \
        (d1) = q0 ? (d0) : (q1 ? (tt) : (d1));                  \
        (i1) = q0 ? (i0) : (q1 ? (nn_) : (i1));                 \
        (d0) = q0 ? (tt) : (d0);                                \
        (i0) = q0 ? (nn_) : (i0);                               \
    } while (0)

#define DRAIN(bal, tval, d0, i0, d1, i1, d2, i2, nbase)        \
    while (bal) {                                               \
        int s = __ffs(bal) - 1; bal &= bal - 1;                 \
        float tt = __shfl_sync(FULLM, tval, s);                 \
        int nn_ = (nbase) + s;                                  \
        INSERT3(tt, nn_, d0, i0, d1, i1, d2, i2);               \
    }

// ---------------- stage D: partial top-3 per (corner, segment), warm-start bound ----------------
__global__ void __launch_bounds__(256) threenn_part_kernel()
{
    int tid = threadIdx.x, lane = tid & 31, wid = tid >> 5;
    int box = blockIdx.x >> 1;                    // 2 blocks per box (x)
    int seg = blockIdx.y;                         // 0..3
    int b = box >> 7, p = box & 127;
    int g = (blockIdx.x & 1)*8 + wid;             // corner group 0..15
    int k0 = g*4;
    int mg = b*M_TOT + p*64 + k0;                 // global corner of A
    size_t cb = (size_t)mg*3;

    float c2A, axA, ayA, azA, c2B, axB, ayB, azB;
    float c2C, axC, ayC, azC, c2D, axD, ayD, azD;
    {
        float x, y, z;
        x = g_cor[cb+0];  y = g_cor[cb+1];  z = g_cor[cb+2];
        c2A = x*x+y*y+z*z; axA = -2.0f*x; ayA = -2.0f*y; azA = -2.0f*z;
        x = g_cor[cb+3];  y = g_cor[cb+4];  z = g_cor[cb+5];
        c2B = x*x+y*y+z*z; axB = -2.0f*x; ayB = -2.0f*y; azB = -2.0f*z;
        x = g_cor[cb+6];  y = g_cor[cb+7];  z = g_cor[cb+8];
        c2C = x*x+y*y+z*z; axC = -2.0f*x; ayC = -2.0f*y; azC = -2.0f*z;
        x = g_cor[cb+9];  y = g_cor[cb+10]; z = g_cor[cb+11];
        c2D = x*x+y*y+z*z; axD = -2.0f*x; ayD = -2.0f*y; azD = -2.0f*z;
    }

    int cnt = g_ccnt[box];
    float B2 = g_B2[box];                         // warm-start bound (all true top-3 < B2)
    int per = (cnt + NSEG - 1) / NSEG;
    int s0 = seg*per;
    int s1 = min(s0 + per, cnt);
    const float4* CP = g_cpts + (size_t)box*CAP;
    const int*    CI = g_cidx + (size_t)box*CAP;

    float dA0=B2,dA1=B2,dA2=B2; int iA0=-1,iA1=-1,iA2=-1;
    float dB0=B2,dB1=B2,dB2=B2; int iB0=-1,iB1=-1,iB2=-1;
    float dC0=B2,dC1=B2,dC2=B2; int iC0=-1,iC1=-1,iC2=-1;
    float dD0=B2,dD1=B2,dD2=B2; int iD0=-1,iD1=-1,iD2=-1;

    if (s0 < s1) {
        int pos0 = s0 + lane;
        float4 pt = CP[min(pos0, cnt-1)];
        if (pos0 >= s1) pt.w = 1e30f;
        for (int base = s0; base < s1; base += 32) {
            float4 cur = pt;
            int nbase2 = base + 32;
            if (nbase2 < s1) {
                int np = nbase2 + lane;
                pt = CP[min(np, cnt-1)];
                if (np >= s1) pt.w = 1e30f;
            }
            float tA = fmaf(axA, cur.x, cur.w + c2A); tA = fmaf(ayA, cur.y, tA); tA = fmaf(azA, cur.z, tA);
            float tB = fmaf(axB, cur.x, cur.w + c2B); tB = fmaf(ayB, cur.y, tB); tB = fmaf(azB, cur.z, tB);
            float tC = fmaf(axC, cur.x, cur.w + c2C); tC = fmaf(ayC, cur.y, tC); tC = fmaf(azC, cur.z, tC);
            float tD = fmaf(axD, cur.x, cur.w + c2D); tD = fmaf(ayD, cur.y, tD); tD = fmaf(azD, cur.z, tD);
            bool hit = (tA < dA2) | (tB < dB2) | (tC < dC2) | (tD < dD2);
            if (__any_sync(FULLM, hit)) {
                unsigned bal;
                bal = __ballot_sync(FULLM, tA < dA2); DRAIN(bal, tA, dA0, iA0, dA1, iA1, dA2, iA2, base);
                bal = __ballot_sync(FULLM, tB < dB2); DRAIN(bal, tB, dB0, iB0, dB1, iB1, dB2, iB2, base);
                bal = __ballot_sync(FULLM, tC < dC2); DRAIN(bal, tC, dC0, iC0, dC1, iC1, dC2, iC2, base);
                bal = __ballot_sync(FULLM, tD < dD2); DRAIN(bal, tD, dD0, iD0, dD1, iD1, dD2, iD2, base);
            }
        }
    }
    if (lane == 0) {
        size_t pb = ((size_t)mg*NSEG + seg)*3;
        g_pd[pb+0] = (iA0 >= 0) ? dA0 : 1e30f; g_pi[pb+0] = (iA0 >= 0) ? CI[iA0] : 0;
        g_pd[pb+1] = (iA1 >= 0) ? dA1 : 1e30f; g_pi[pb+1] = (iA1 >= 0) ? CI[iA1] : 0;
        g_pd[pb+2] = (iA2 >= 0) ? dA2 : 1e30f; g_pi[pb+2] = (iA2 >= 0) ? CI[iA2] : 0;
        pb += (size_t)NSEG*3;
        g_pd[pb+0] = (iB0 >= 0) ? dB0 : 1e30f; g_pi[pb+0] = (iB0 >= 0) ? CI[iB0] : 0;
        g_pd[pb+1] = (iB1 >= 0) ? dB1 : 1e30f; g_pi[pb+1] = (iB1 >= 0) ? CI[iB1] : 0;
        g_pd[pb+2] = (iB2 >= 0) ? dB2 : 1e30f; g_pi[pb+2] = (iB2 >= 0) ? CI[iB2] : 0;
        pb += (size_t)NSEG*3;
        g_pd[pb+0] = (iC0 >= 0) ? dC0 : 1e30f; g_pi[pb+0] = (iC0 >= 0) ? CI[iC0] : 0;
        g_pd[pb+1] = (iC1 >= 0) ? dC1 : 1e30f; g_pi[pb+1] = (iC1 >= 0) ? CI[iC1] : 0;
        g_pd[pb+2] = (iC2 >= 0) ? dC2 : 1e30f; g_pi[pb+2] = (iC2 >= 0) ? CI[iC2] : 0;
        pb += (size_t)NSEG*3;
        g_pd[pb+0] = (iD0 >= 0) ? dD0 : 1e30f; g_pi[pb+0] = (iD0 >= 0) ? CI[iD0] : 0;
        g_pd[pb+1] = (iD1 >= 0) ? dD1 : 1e30f; g_pi[pb+1] = (iD1 >= 0) ? CI[iD1] : 0;
        g_pd[pb+2] = (iD2 >= 0) ? dD2 : 1e30f; g_pi[pb+2] = (iD2 >= 0) ? CI[iD2] : 0;
    }
}

// ---------------- merge: combine 4 segment partials per corner, write weights ----------------
__global__ void __launch_bounds__(256) merge_kernel(const float* __restrict__ oxyz)
{
    int mg = blockIdx.x*256 + threadIdx.x;        // 0..16383
    int b = mg >> 13;
    const float* O = oxyz + (size_t)b*NN*3;
    size_t pb = (size_t)mg*NSEG*3;
    float d0 = 1e30f, d1 = 1e30f, d2 = 1e30f;
    int i0 = 0, i1 = 0, i2 = 0;
    #pragma unroll
    for (int s = 0; s < NSEG*3; s++) {
        float dv = g_pd[pb + s];
        int   iv = g_pi[pb + s];
        INSERT3(dv, iv, d0, i0, d1, i1, d2, i2);
    }
    size_t cb = (size_t)mg*3;
    float cx = g_cor[cb+0], cy = g_cor[cb+1], cz = g_cor[cb+2];
    int win[3] = {i0, i1, i2};
    float w[3], ssum = 0.0f;
    #pragma unroll
    for (int r = 0; r < 3; r++) {
        const float* P = O + (size_t)win[r]*3;
        float dx = P[0]-cx, dy = P[1]-cy, dz = P[2]-cz;
        float d = sqrtf(dx*dx + dy*dy + dz*dz);
        w[r] = 1.0f / (d + 1e-8f);
        ssum += w[r];
    }
    float inv = 1.0f/ssum;
    #pragma unroll
    for (int r = 0; r < 3; r++) { g_nni[cb+r] = win[r]; g_nnw[cb+r] = w[r]*inv; }
}

// ---------------- gemm_G: 128n x 64o, BK=16, 8x4, double-buffered (proven) ----------------
__global__ void __launch_bounds__(256) gemmG_kernel(const float* __restrict__ feat)
{
    __shared__ float Ns[2][16][132];
    __shared__ float Os[2][16][64];
    int n0 = blockIdx.x*128, o0 = blockIdx.y*64, b = blockIdx.z;
    int tid = threadIdx.x;
    int kr  = tid >> 4;
    int nc  = (tid & 15)*8;
    int oc  = (tid & 15)*4;
    int tr  = (tid >> 4)*8;
    int tc  = (tid & 15)*4;
    const float* F = feat + (size_t)b*CC*NN;

    float acc[8][4] = {};
    float4 na0, na1, nb;
    na0 = *(const float4*)&F[(size_t)kr*NN + n0 + nc];
    na1 = *(const float4*)&F[(size_t)kr*NN + n0 + nc + 4];
    nb  = *(const float4*)&g_w1T[kr*128 + o0 + oc];
    *(float4*)&Ns[0][kr][nc]   = na0;
    *(float4*)&Ns[0][kr][nc+4] = na1;
    *(float4*)&Os[0][kr][oc]   = nb;
    __syncthreads();
    int buf = 0;
    #pragma unroll 1
    for (int kb = 0; kb < 8; kb++) {
        bool has = kb < 7;
        if (has) {
            int kk = (kb+1)*16 + kr;
            na0 = *(const float4*)&F[(size_t)kk*NN + n0 + nc];
            na1 = *(const float4*)&F[(size_t)kk*NN + n0 + nc + 4];
            nb  = *(const float4*)&g_w1T[kk*128 + o0 + oc];
        }
        #pragma unroll
        for (int k = 0; k < 16; k++) {
            float4 a0 = *(const float4*)&Ns[buf][k][tr];
            float4 a1 = *(const float4*)&Ns[buf][k][tr+4];
            float4 bq = *(const float4*)&Os[buf][k][tc];
            float ar[8] = {a0.x,a0.y,a0.z,a0.w,a1.x,a1.y,a1.z,a1.w};
            float br[4] = {bq.x,bq.y,bq.z,bq.w};
            #pragma unroll
            for (int i = 0; i < 8; i++)
                #pragma unroll
                for (int j = 0; j < 4; j++)
                    acc[i][j] = fmaf(ar[i], br[j], acc[i][j]);
        }
        if (has) {
            int nbuf = buf^1;
            *(float4*)&Ns[nbuf][kr][nc]   = na0;
            *(float4*)&Ns[nbuf][kr][nc+4] = na1;
            *(float4*)&Os[nbuf][kr][oc]   = nb;
            __syncthreads();
            buf = nbuf;
        }
    }
    float* Gp = g_G + ((size_t)b*NN + n0 + tr)*128 + o0 + tc;
    #pragma unroll
    for (int i = 0; i < 8; i++) {
        float4 v = {acc[i][0], acc[i][1], acc[i][2], acc[i][3]};
        *(float4*)(Gp + (size_t)i*128) = v;
    }
}

// ---------------- combine v2: block = 32 corners, coalesced h1T row writes ----------------
__global__ void __launch_bounds__(256) combine_kernel(const float* __restrict__ w1,
                                                      const float* __restrict__ b1)
{
    __shared__ float wr0[128], wr1[128], wr2[128], sb[128];
    __shared__ float tr[128][33];
    int tid = threadIdx.x, lane = tid & 31, wid = tid >> 5;
    if (tid < 128) {
        const float* wrow = w1 + tid*131;
        wr0[tid] = wrow[0]; wr1[tid] = wrow[1]; wr2[tid] = wrow[2];
        sb[tid]  = b1[tid];
    }
    __syncthreads();
    int m0 = blockIdx.x*32;
    #pragma unroll 1
    for (int cc = 0; cc < 4; cc++) {
        int ml = wid*4 + cc;                         // 0..31 local corner
        int m  = m0 + ml;
        int b = m >> 13, mb = m & 8191;
        size_t base3 = ((size_t)b*M_TOT + mb)*3;
        int i0 = g_nni[base3+0], i1 = g_nni[base3+1], i2 = g_nni[base3+2];
        float w0 = g_nnw[base3+0], w1w = g_nnw[base3+1], w2w = g_nnw[base3+2];
        float rx = g_rel[(size_t)m*3+0], ry = g_rel[(size_t)m*3+1], rz = g_rel[(size_t)m*3+2];
        const float* G0 = g_G + ((size_t)b*NN + i0)*128;
        const float* G1 = g_G + ((size_t)b*NN + i1)*128;
        const float* G2 = g_G + ((size_t)b*NN + i2)*128;
        int c0 = lane*4;
        float4 a  = *(const float4*)(G0 + c0);
        float4 bq = *(const float4*)(G1 + c0);
        float4 cq = *(const float4*)(G2 + c0);
        float va[4] = {a.x,a.y,a.z,a.w};
        float vb[4] = {bq.x,bq.y,bq.z,bq.w};
        float vc[4] = {cq.x,cq.y,cq.z,cq.w};
        #pragma unroll
        for (int j = 0; j < 4; j++) {
            int o = c0 + j;
            float acc = w0*va[j] + w1w*vb[j] + w2w*vc[j];
            acc = fmaf(rx, wr0[o], acc);
            acc = fmaf(ry, wr1[o], acc);
            acc = fmaf(rz, wr2[o], acc);
            tr[o][ml] = fmaxf(acc + sb[o], 0.0f);
        }
    }
    __syncthreads();
    int c = tid >> 1, base = (tid & 1)*16;
    float* dst = &g_h1T[(size_t)c*MG + m0 + base];
    #pragma unroll
    for (int q = 0; q < 4; q++) {
        float4 v = {tr[c][base+q*4+0], tr[c][base+q*4+1], tr[c][base+q*4+2], tr[c][base+q*4+3]};
        *(float4*)(dst + q*4) = v;
    }
}

// ---------------- gemm2 (tf32 tensor-core) + fused relu + maxpool over 64 ----------------
__global__ void __launch_bounds__(256) gemm2_pool_kernel(const float* __restrict__ bias)
{
    __shared__ float As[2][16][132];     // [k][m], padded
    __shared__ float Bs[2][16][68];      // [k][o], padded
    __shared__ int spool[128];           // [2 pool-groups][64 o]
    int m0 = blockIdx.x*128, o0 = blockIdx.y*64;
    int tid = threadIdx.x, lane = tid & 31, wid = tid >> 5;
    int wm = wid >> 1, wn = wid & 1;
    int kr = tid >> 4, c16 = tid & 15;
    if (tid < 128) spool[tid] = 0;

    float acc[2][4][4] = {};

    {
        const float* ap = &g_h1T[(size_t)kr*MG + m0 + c16*8];
        float4 a0 = *(const float4*)ap;
        float4 a1 = *(const float4*)(ap + 4);
        float* d = &As[0][kr][c16*8];
        d[0]=tf32r(a0.x); d[1]=tf32r(a0.y); d[2]=tf32r(a0.z); d[3]=tf32r(a0.w);
        d[4]=tf32r(a1.x); d[5]=tf32r(a1.y); d[6]=tf32r(a1.z); d[7]=tf32r(a1.w);
        float4 bv = *(const float4*)&g_w2T[kr*256 + o0 + c16*4];
        float* e = &Bs[0][kr][c16*4];
        e[0]=tf32r(bv.x); e[1]=tf32r(bv.y); e[2]=tf32r(bv.z); e[3]=tf32r(bv.w);
    }
    __syncthreads();

    int buf = 0;
    int lk = lane & 3, lr = lane >> 2;
    #pragma unroll 1
    for (int kb = 0; kb < 8; kb++) {
        bool has = kb < 7;
        float4 na0, na1, nb;
        if (has) {
            int kk = (kb+1)*16 + kr;
            const float* ap = &g_h1T[(size_t)kk*MG + m0 + c16*8];
            na0 = *(const float4*)ap;
            na1 = *(const float4*)(ap + 4);
            nb  = *(const float4*)&g_w2T[kk*256 + o0 + c16*4];
        }
        #pragma unroll
        for (int ks = 0; ks < 2; ks++) {
            int klo = ks*8 + lk;
            uint32_t afr[2][4];
            #pragma unroll
            for (int mt = 0; mt < 2; mt++) {
                int mr = wm*32 + mt*16 + lr;
                afr[mt][0] = __float_as_uint(As[buf][klo  ][mr]);
                afr[mt][1] = __float_as_uint(As[buf][klo  ][mr+8]);
                afr[mt][2] = __float_as_uint(As[buf][klo+4][mr]);
                afr[mt][3] = __float_as_uint(As[buf][klo+4][mr+8]);
            }
            uint32_t bfr[4][2];
            #pragma unroll
            for (int nt = 0; nt < 4; nt++) {
                int nr = wn*32 + nt*8 + lr;
                bfr[nt][0] = __float_as_uint(Bs[buf][klo  ][nr]);
                bfr[nt][1] = __float_as_uint(Bs[buf][klo+4][nr]);
            }
            #pragma unroll
            for (int mt = 0; mt < 2; mt++)
                #pragma unroll
                for (int nt = 0; nt < 4; nt++)
                    mma_tf32(acc[mt][nt], afr[mt], bfr[nt]);
        }
        if (has) {
            int nbuf = buf^1;
            float* d = &As[nbuf][kr][c16*8];
            d[0]=tf32r(na0.x); d[1]=tf32r(na0.y); d[2]=tf32r(na0.z); d[3]=tf32r(na0.w);
            d[4]=tf32r(na1.x); d[5]=tf32r(na1.y); d[6]=tf32r(na1.z); d[7]=tf32r(na1.w);
            float* e = &Bs[nbuf][kr][c16*4];
            e[0]=tf32r(nb.x); e[1]=tf32r(nb.y); e[2]=tf32r(nb.z); e[3]=tf32r(nb.w);
            __syncthreads();
            buf = nbuf;
        }
    }

    int grp = wm >> 1;
    #pragma unroll
    for (int nt = 0; nt < 4; nt++) {
        int c0 = wn*32 + nt*8 + (lane & 3)*2;
        float b0v = bias[o0 + c0], b1v = bias[o0 + c0 + 1];
        float p0v = 0.0f, p1v = 0.0f;
        #pragma unroll
        for (int mt = 0; mt < 2; mt++) {
            p0v = fmaxf(p0v, acc[mt][nt][0] + b0v);
            p0v = fmaxf(p0v, acc[mt][nt][2] + b0v);
            p1v = fmaxf(p1v, acc[mt][nt][1] + b1v);
            p1v = fmaxf(p1v, acc[mt][nt][3] + b1v);
        }
        atomicMax(&spool[grp*64 + c0],     __float_as_int(p0v));
        atomicMax(&spool[grp*64 + c0 + 1], __float_as_int(p1v));
    }
    __syncthreads();
    if (tid < 128) {
        int g = tid >> 6, ol = tid & 63;
        int b  = m0 >> 13;
        int p0 = (m0 >> 6) & 127;
        g_pool[((size_t)b*256 + o0 + ol)*NPT + p0 + g] = __int_as_float(spool[g*64 + ol]);
    }
}

// ---------------- fused linear + train-mode BN + relu ----------------
__global__ void lin_bn_kernel(const float* __restrict__ W, const float* __restrict__ bias,
                              const float* __restrict__ gam, const float* __restrict__ bet,
                              int stage)
{
    int o = blockIdx.x, tid = threadIdx.x;            // 256 threads = (b,p)
    int b = tid >> 7, p = tid & 127;
    int K = stage ? 128 : 256;
    const float* X = stage ? g_z0 : g_pool;
    __shared__ float ws[256];
    if (tid < K) ws[tid] = W[o*K + tid];
    __syncthreads();
    const float* Xb = X + (size_t)b*K*NPT + p;
    float acc = bias[o];
    #pragma unroll 8
    for (int c = 0; c < K; c++) acc = fmaf(ws[c], Xb[(size_t)c*NPT], acc);
    __shared__ float red[256];
    red[tid] = acc; __syncthreads();
    #pragma unroll
    for (int s = 128; s > 0; s >>= 1) { if (tid < s) red[tid] += red[tid+s]; __syncthreads(); }
    float mean = red[0] * (1.0f/256.0f);
    __syncthreads();
    float d = acc - mean;
    red[tid] = d*d; __syncthreads();
    #pragma unroll
    for (int s = 128; s > 0; s >>= 1) { if (tid < s) red[tid] += red[tid+s]; __syncthreads(); }
    float var = red[0] * (1.0f/256.0f);
    float z = d * rsqrtf(var + 1e-5f) * gam[o] + bet[o];
    float* Y = stage ? g_z1 : g_z0;
    Y[((size_t)b*128 + o)*NPT + p] = fmaxf(z, 0.0f);
}

__global__ void final_kernel(const float* __restrict__ W, const float* __restrict__ bias,
                             float* __restrict__ out)
{
    int b = blockIdx.x, p = threadIdx.x;
    const float* Z = g_z1 + (size_t)b*128*NPT;
    float acc = bias[0];
    #pragma unroll 8
    for (int c = 0; c < 128; c++) acc = fmaf(W[c], Z[(size_t)c*NPT + p], acc);
    out[b*NPT + p] = acc;
}

// ---------------- launch ----------------
extern "C" void kernel_launch(void* const* d_in, const int* in_sizes, int n_in,
                              void* d_out, int out_size)
{
    const float* oxyz  = (const float*)d_in[0];
    const float* ofeat = (const float*)d_in[1];
    const float* cand  = (const float*)d_in[2];
    // d_in[3] = pred_cls (unused)
    const float* poff  = (const float*)d_in[4];
    const float* pacls = (const float*)d_in[5];
    const float* pares = (const float*)d_in[6];
    const float* w1    = (const float*)d_in[7];
    const float* b1    = (const float*)d_in[8];
    const float* w2    = (const float*)d_in[9];
    const float* b2    = (const float*)d_in[10];
    const float* wi0   = (const float*)d_in[11];
    const float* bi0   = (const float*)d_in[12];
    const float* gi0   = (const float*)d_in[13];
    const float* bei0  = (const float*)d_in[14];
    const float* wi1   = (const float*)d_in[15];
    const float* bi1   = (const float*)d_in[16];
    const float* gi1   = (const float*)d_in[17];
    const float* bei1  = (const float*)d_in[18];
    const float* wi2   = (const float*)d_in[19];
    const float* bi2   = (const float*)d_in[20];
    float* out = (float*)d_out;

    setup_kernel<<<320, 256>>>(cand, poff, pacls, pares, oxyz, w1, w2);  // #1
    prune_kernel<<<256, 256>>>(oxyz);                                    // #2 (center3+compact)
    threenn_part_kernel<<<dim3(512, NSEG), 256>>>();                     // #3
    merge_kernel<<<64, 256>>>(oxyz);                                     // #4
    gemmG_kernel<<<dim3(64, 2, 2), 256>>>(ofeat);                        // #5
    combine_kernel<<<512, 256>>>(w1, b1);                                // #6
    gemm2_pool_kernel<<<dim3(128, 4), 256>>>(b2);                        // #7
    lin_bn_kernel<<<128, 256>>>(wi0, bi0, gi0, bei0, 0);                 // #8
    lin_bn_kernel<<<128, 256>>>(wi1, bi1, gi1, bei1, 1);                 // #9
    final_kernel<<<2, 128>>>(wi2, bi2, out);                             // #10
}

// round 17
// speedup vs baseline: 1.4178x; 1.0058x over previous
#include <cuda_runtime.h>
#include <math.h>
#include <stdint.h>

#define BS2   2
#define NN    8192
#define NPT   128
#define CC    128
#define M_TOT 8192        // NPT*64 per batch
#define MG    16384       // total corners
#define NBOX  256         // BS2*NPT
#define CAP   8192        // max candidates per box
#define NSEG  4
#define FULLM 0xffffffffu

// ---------------- device scratch ----------------
static __device__ float g_p2[(size_t)BS2*NN];
static __device__ float g_rel[(size_t)MG*3];
static __device__ float g_cor[(size_t)MG*3];
static __device__ int   g_nni[(size_t)MG*3];
static __device__ float g_nnw[(size_t)MG*3];
static __device__ float g_ctr[NBOX*3];
static __device__ float g_md[NBOX];
static __device__ float g_B2[NBOX];
static __device__ float4 g_cpts[(size_t)NBOX*CAP];
static __device__ int    g_cidx[(size_t)NBOX*CAP];
static __device__ int    g_ccnt[NBOX];
static __device__ float g_pd[(size_t)MG*NSEG*3];
static __device__ int   g_pi[(size_t)MG*NSEG*3];
static __device__ float g_w1T[128*128];                 // [k][o]
static __device__ float g_w2T[128*256];                 // [k][o]
static __device__ float g_G[(size_t)BS2*NN*128];        // [b][n][o] = W1f . f
static __device__ float g_h1T[(size_t)128*MG];          // [c][m]
static __device__ float g_pool[(size_t)BS2*256*NPT];    // [b][o][p]
static __device__ float g_z0[(size_t)BS2*128*NPT];
static __device__ float g_z1[(size_t)BS2*128*NPT];

__device__ __forceinline__ float tf32r(float x) {
    uint32_t u; asm("cvt.rna.tf32.f32 %0, %1;" : "=r"(u) : "f"(x));
    return __uint_as_float(u);
}

__device__ __forceinline__ void mma_tf32(float c[4], const uint32_t a[4], const uint32_t b[2]) {
    asm volatile(
        "mma.sync.aligned.m16n8k8.row.col.f32.tf32.tf32.f32 "
        "{%0,%1,%2,%3}, {%4,%5,%6,%7}, {%8,%9}, {%0,%1,%2,%3};\n"
        : "+f"(c[0]), "+f"(c[1]), "+f"(c[2]), "+f"(c[3])
        : "r"(a[0]), "r"(a[1]), "r"(a[2]), "r"(a[3]), "r"(b[0]), "r"(b[1]));
}

// ---------------- setup: decode + p2 + box meta + weight transposes ----------------
__global__ void setup_kernel(const float* __restrict__ cand,
                             const float* __restrict__ off,
                             const float* __restrict__ acls,
                             const float* __restrict__ ares,
                             const float* __restrict__ oxyz,
                             const float* __restrict__ w1,
                             const float* __restrict__ w2)
{
    int bx = blockIdx.x, tid = threadIdx.x;
    if (bx < 64) {
        int t = bx*256 + tid;                        // 16384 = b*8192 + p*64 + k
        int k  = t & 63;
        int bp = t >> 6;
        const float* a = acls + bp*12;
        float best = a[0]; int bi = 0;
        #pragma unroll
        for (int j = 1; j < 12; j++) { float v = a[j]; if (v > best) { best = v; bi = j; } }
        float res = ares[bp*12 + bi];
        const float PI_F = 3.14159265358979323846f;
        float ang = (float)bi * (float)(2.0*3.14159265358979323846/12.0) + res;
        float heading = (ang > PI_F) ? (ang - 2.0f*PI_F) : ang;
        float s, c; sincosf(heading, &s, &c);
        const float* o6 = off + bp*6;
        float cx = cand[bp*3+0] + o6[0];
        float cy = cand[bp*3+1] + o6[1];
        float cz = cand[bp*3+2] + o6[2];
        float lx = fmaxf(o6[3]*2.0f, 0.1f);
        float ly = fmaxf(o6[4]*2.0f, 0.1f);
        float lz = fmaxf(o6[5]*2.0f, 0.1f);
        if (k == 0) {
            g_ctr[bp*3+0] = cx; g_ctr[bp*3+1] = cy; g_ctr[bp*3+2] = cz;
            g_md[bp] = sqrtf(lx*lx + ly*ly + lz*lz);
        }
        float gv[4] = {-1.0f, -1.0f/3.0f, 1.0f/3.0f, 1.0f};
        float gx = gv[(k>>4)&3] * lx;
        float gy = gv[(k>>2)&3] * ly;
        float gz = gv[k&3]      * lz;
        float rx = gx*c - gy*s;
        float ry = gx*s + gy*c;
        float rz = gz;
        size_t b3 = (size_t)t*3;
        g_rel[b3+0] = rx; g_rel[b3+1] = ry; g_rel[b3+2] = rz;
        g_cor[b3+0] = rx + cx; g_cor[b3+1] = ry + cy; g_cor[b3+2] = rz + cz;
    } else if (bx < 128) {
        int t = (bx-64)*256 + tid;
        float x = oxyz[t*3], y = oxyz[t*3+1], z = oxyz[t*3+2];
        g_p2[t] = x*x + y*y + z*z;
    } else if (bx < 192) {
        int t = (bx-128)*256 + tid;                  // 16384 = k*128+o
        int o = t & 127, k = t >> 7;
        g_w1T[t] = w1[o*131 + 3 + k];
    } else {
        int t = (bx-192)*256 + tid;                  // 32768 = k*256+o
        int o = t & 255, k = t >> 8;
        g_w2T[t] = w2[o*128 + k];
    }
}

// values-only top-3 insert
#define INSERT3V(tt, d0, d1, d2)                               \
    do {                                                        \
        bool q2 = (tt) < (d2), q1 = (tt) < (d1), q0 = (tt) < (d0); \
        (d2) = q1 ? (d1) : (q2 ? (tt) : (d2));                  \
        (d1) = q0 ? (d0) : (q1 ? (tt) : (d1));                  \
        (d0) = q0 ? (tt) : (d0);                                \
    } while (0)

// ---------------- prune: per-box center-d3 then compaction (fused) ----------------
__global__ void __launch_bounds__(256) prune_kernel(const float* __restrict__ oxyz)
{
    __shared__ float s_d[24];
    __shared__ float s_R2;
    __shared__ int s_warp[8];
    __shared__ int s_base;
    int box = blockIdx.x;                         // 0..255
    int b = box >> 7;
    int tid = threadIdx.x, lane = tid & 31, wid = tid >> 5;
    const float* O = oxyz + (size_t)b*NN*3;
    const float* Q = g_p2 + (size_t)b*NN;
    float cx = g_ctr[box*3+0], cy = g_ctr[box*3+1], cz = g_ctr[box*3+2];
    float c2 = cx*cx + cy*cy + cz*cz;
    float ax = -2.0f*cx, ay = -2.0f*cy, az = -2.0f*cz;

    // phase 1: exact center d3
    float d0 = 1e30f, d1 = 1e30f, d2v = 1e30f;
    for (int n = wid*1024 + lane; n < (wid+1)*1024; n += 32) {
        float t = Q[n] + c2;
        t = fmaf(ax, O[n*3+0], t);
        t = fmaf(ay, O[n*3+1], t);
        t = fmaf(az, O[n*3+2], t);
        if (t < d2v) INSERT3V(t, d0, d1, d2v);
    }
    #pragma unroll
    for (int offi = 16; offi; offi >>= 1) {
        float e0 = __shfl_xor_sync(FULLM, d0, offi);
        float e1 = __shfl_xor_sync(FULLM, d1, offi);
        float e2 = __shfl_xor_sync(FULLM, d2v, offi);
        INSERT3V(e0, d0, d1, d2v);
        INSERT3V(e1, d0, d1, d2v);
        INSERT3V(e2, d0, d1, d2v);
    }
    if (lane == 0) { s_d[wid*3+0] = d0; s_d[wid*3+1] = d1; s_d[wid*3+2] = d2v; }
    if (tid == 0) s_base = 0;
    __syncthreads();
    if (tid == 0) {
        float f0 = 1e30f, f1 = 1e30f, f2 = 1e30f;
        #pragma unroll
        for (int i = 0; i < 24; i++) INSERT3V(s_d[i], f0, f1, f2);
        float d3 = sqrtf(fmaxf(f2, 0.0f));
        float md = g_md[box];
        float r = d3 + 2.0f*md + 1e-2f;
        s_R2 = r*r*1.0001f + 1e-3f;
        float bb = d3 + md + 1e-2f;
        g_B2[box] = bb*bb*1.0001f + 1e-3f;
    }
    __syncthreads();
    float R2 = s_R2;

    // phase 2: ordered compaction
    float4* CP = g_cpts + (size_t)box*CAP;
    int*    CI = g_cidx + (size_t)box*CAP;
    for (int t0 = 0; t0 < NN; t0 += 256) {
        int n = t0 + tid;
        float x = O[n*3+0], y = O[n*3+1], z = O[n*3+2];
        float p2 = Q[n];
        float d = p2 + c2;
        d = fmaf(ax, x, d); d = fmaf(ay, y, d); d = fmaf(az, z, d);
        bool keep = d <= R2;
        unsigned mask = __ballot_sync(FULLM, keep);
        if (lane == 0) s_warp[wid] = __popc(mask);
        __syncthreads();
        int prev = 0, tot = 0;
        #pragma unroll
        for (int w = 0; w < 8; w++) {
            int cn = s_warp[w];
            if (w < wid) prev += cn;
            tot += cn;
        }
        int pos = s_base + prev + __popc(mask & ((1u << lane) - 1u));
        if (keep) {
            CP[pos] = make_float4(x, y, z, p2);
            CI[pos] = n;
        }
        __syncthreads();
        if (tid == 0) s_base += tot;
        __syncthreads();
    }
    if (tid == 0) g_ccnt[box] = s_base;
}

// warp-uniform insert with index
#define INSERT3(tt, nn_, d0, i0, d1, i1, d2, i2)               \
    do {                                                        \
        bool q2 = (tt) < (d2), q1 = (tt) < (d1), q0 = (tt) < (d0); \
        (d2) = q1 ? (d1) : (q2 ? (tt) : (d2));                  \
        (i2) = q1 ? (i1) : (q2 ? (nn_) : (i2));                 \
        (d1) = q0 ? (d0) : (q1 ? (tt) : (d1));                  \
        (i1) = q0 ? (i0) : (q1 ? (nn_) : (i1));                 \
        (d0) = q0 ? (tt) : (d0);                                \
        (i0) = q0 ? (nn_) : (i0);                               \
    } while (0)

#define DRAIN(bal, tval, d0, i0, d1, i1, d2, i2, nbase)        \
    while (bal) {                                               \
        int s = __ffs(bal) - 1; bal &= bal - 1;                 \
        float tt = __shfl_sync(FULLM, tval, s);                 \
        int nn_ = (nbase) + s;                                  \
        INSERT3(tt, nn_, d0, i0, d1, i1, d2, i2);               \
    }

// ---------------- stage D: partial top-3 per (corner, segment), warm-start bound ----------------
__global__ void __launch_bounds__(256) threenn_part_kernel()
{
    int tid = threadIdx.x, lane = tid & 31, wid = tid >> 5;
    int box = blockIdx.x >> 1;                    // 2 blocks per box (x)
    int seg = blockIdx.y;                         // 0..3
    int b = box >> 7, p = box & 127;
    int g = (blockIdx.x & 1)*8 + wid;             // corner group 0..15
    int k0 = g*4;
    int mg = b*M_TOT + p*64 + k0;                 // global corner of A
    size_t cb = (size_t)mg*3;

    float c2A, axA, ayA, azA, c2B, axB, ayB, azB;
    float c2C, axC, ayC, azC, c2D, axD, ayD, azD;
    {
        float x, y, z;
        x = g_cor[cb+0];  y = g_cor[cb+1];  z = g_cor[cb+2];
        c2A = x*x+y*y+z*z; axA = -2.0f*x; ayA = -2.0f*y; azA = -2.0f*z;
        x = g_cor[cb+3];  y = g_cor[cb+4];  z = g_cor[cb+5];
        c2B = x*x+y*y+z*z; axB = -2.0f*x; ayB = -2.0f*y; azB = -2.0f*z;
        x = g_cor[cb+6];  y = g_cor[cb+7];  z = g_cor[cb+8];
        c2C = x*x+y*y+z*z; axC = -2.0f*x; ayC = -2.0f*y; azC = -2.0f*z;
        x = g_cor[cb+9];  y = g_cor[cb+10]; z = g_cor[cb+11];
        c2D = x*x+y*y+z*z; axD = -2.0f*x; ayD = -2.0f*y; azD = -2.0f*z;
    }

    int cnt = g_ccnt[box];
    float B2 = g_B2[box];                         // warm-start bound (all true top-3 < B2)
    int per = (cnt + NSEG - 1) / NSEG;
    int s0 = seg*per;
    int s1 = min(s0 + per, cnt);
    const float4* CP = g_cpts + (size_t)box*CAP;
    const int*    CI = g_cidx + (size_t)box*CAP;

    float dA0=B2,dA1=B2,dA2=B2; int iA0=-1,iA1=-1,iA2=-1;
    float dB0=B2,dB1=B2,dB2=B2; int iB0=-1,iB1=-1,iB2=-1;
    float dC0=B2,dC1=B2,dC2=B2; int iC0=-1,iC1=-1,iC2=-1;
    float dD0=B2,dD1=B2,dD2=B2; int iD0=-1,iD1=-1,iD2=-1;

    if (s0 < s1) {
        int pos0 = s0 + lane;
        float4 pt = CP[min(pos0, cnt-1)];
        if (pos0 >= s1) pt.w = 1e30f;
        for (int base = s0; base < s1; base += 32) {
            float4 cur = pt;
            int nbase2 = base + 32;
            if (nbase2 < s1) {
                int np = nbase2 + lane;
                pt = CP[min(np, cnt-1)];
                if (np >= s1) pt.w = 1e30f;
            }
            float tA = fmaf(axA, cur.x, cur.w + c2A); tA = fmaf(ayA, cur.y, tA); tA = fmaf(azA, cur.z, tA);
            float tB = fmaf(axB, cur.x, cur.w + c2B); tB = fmaf(ayB, cur.y, tB); tB = fmaf(azB, cur.z, tB);
            float tC = fmaf(axC, cur.x, cur.w + c2C); tC = fmaf(ayC, cur.y, tC); tC = fmaf(azC, cur.z, tC);
            float tD = fmaf(axD, cur.x, cur.w + c2D); tD = fmaf(ayD, cur.y, tD); tD = fmaf(azD, cur.z, tD);
            bool hit = (tA < dA2) | (tB < dB2) | (tC < dC2) | (tD < dD2);
            if (__any_sync(FULLM, hit)) {
                unsigned bal;
                bal = __ballot_sync(FULLM, tA < dA2); DRAIN(bal, tA, dA0, iA0, dA1, iA1, dA2, iA2, base);
                bal = __ballot_sync(FULLM, tB < dB2); DRAIN(bal, tB, dB0, iB0, dB1, iB1, dB2, iB2, base);
                bal = __ballot_sync(FULLM, tC < dC2); DRAIN(bal, tC, dC0, iC0, dC1, iC1, dC2, iC2, base);
                bal = __ballot_sync(FULLM, tD < dD2); DRAIN(bal, tD, dD0, iD0, dD1, iD1, dD2, iD2, base);
            }
        }
    }
    if (lane == 0) {
        size_t pb = ((size_t)mg*NSEG + seg)*3;
        g_pd[pb+0] = (iA0 >= 0) ? dA0 : 1e30f; g_pi[pb+0] = (iA0 >= 0) ? CI[iA0] : 0;
        g_pd[pb+1] = (iA1 >= 0) ? dA1 : 1e30f; g_pi[pb+1] = (iA1 >= 0) ? CI[iA1] : 0;
        g_pd[pb+2] = (iA2 >= 0) ? dA2 : 1e30f; g_pi[pb+2] = (iA2 >= 0) ? CI[iA2] : 0;
        pb += (size_t)NSEG*3;
        g_pd[pb+0] = (iB0 >= 0) ? dB0 : 1e30f; g_pi[pb+0] = (iB0 >= 0) ? CI[iB0] : 0;
        g_pd[pb+1] = (iB1 >= 0) ? dB1 : 1e30f; g_pi[pb+1] = (iB1 >= 0) ? CI[iB1] : 0;
        g_pd[pb+2] = (iB2 >= 0) ? dB2 : 1e30f; g_pi[pb+2] = (iB2 >= 0) ? CI[iB2] : 0;
        pb += (size_t)NSEG*3;
        g_pd[pb+0] = (iC0 >= 0) ? dC0 : 1e30f; g_pi[pb+0] = (iC0 >= 0) ? CI[iC0] : 0;
        g_pd[pb+1] = (iC1 >= 0) ? dC1 : 1e30f; g_pi[pb+1] = (iC1 >= 0) ? CI[iC1] : 0;
        g_pd[pb+2] = (iC2 >= 0) ? dC2 : 1e30f; g_pi[pb+2] = (iC2 >= 0) ? CI[iC2] : 0;
        pb += (size_t)NSEG*3;
        g_pd[pb+0] = (iD0 >= 0) ? dD0 : 1e30f; g_pi[pb+0] = (iD0 >= 0) ? CI[iD0] : 0;
        g_pd[pb+1] = (iD1 >= 0) ? dD1 : 1e30f; g_pi[pb+1] = (iD1 >= 0) ? CI[iD1] : 0;
        g_pd[pb+2] = (iD2 >= 0) ? dD2 : 1e30f; g_pi[pb+2] = (iD2 >= 0) ? CI[iD2] : 0;
    }
}

// ---------------- merge: combine 4 segment partials per corner, write weights ----------------
__global__ void __launch_bounds__(256) merge_kernel(const float* __restrict__ oxyz)
{
    int mg = blockIdx.x*256 + threadIdx.x;        // 0..16383
    int b = mg >> 13;
    const float* O = oxyz + (size_t)b*NN*3;
    size_t pb = (size_t)mg*NSEG*3;
    float d0 = 1e30f, d1 = 1e30f, d2 = 1e30f;
    int i0 = 0, i1 = 0, i2 = 0;
    #pragma unroll
    for (int s = 0; s < NSEG*3; s++) {
        float dv = g_pd[pb + s];
        int   iv = g_pi[pb + s];
        INSERT3(dv, iv, d0, i0, d1, i1, d2, i2);
    }
    size_t cb = (size_t)mg*3;
    float cx = g_cor[cb+0], cy = g_cor[cb+1], cz = g_cor[cb+2];
    int win[3] = {i0, i1, i2};
    float w[3], ssum = 0.0f;
    #pragma unroll
    for (int r = 0; r < 3; r++) {
        const float* P = O + (size_t)win[r]*3;
        float dx = P[0]-cx, dy = P[1]-cy, dz = P[2]-cz;
        float d = sqrtf(dx*dx + dy*dy + dz*dz);
        w[r] = 1.0f / (d + 1e-8f);
        ssum += w[r];
    }
    float inv = 1.0f/ssum;
    #pragma unroll
    for (int r = 0; r < 3; r++) { g_nni[cb+r] = win[r]; g_nnw[cb+r] = w[r]*inv; }
}

// ---------------- gemm_G: 128n x 64o, BK=16, 8x4, double-buffered (proven) ----------------
__global__ void __launch_bounds__(256) gemmG_kernel(const float* __restrict__ feat)
{
    __shared__ float Ns[2][16][132];
    __shared__ float Os[2][16][64];
    int n0 = blockIdx.x*128, o0 = blockIdx.y*64, b = blockIdx.z;
    int tid = threadIdx.x;
    int kr  = tid >> 4;
    int nc  = (tid & 15)*8;
    int oc  = (tid & 15)*4;
    int tr  = (tid >> 4)*8;
    int tc  = (tid & 15)*4;
    const float* F = feat + (size_t)b*CC*NN;

    float acc[8][4] = {};
    float4 na0, na1, nb;
    na0 = *(const float4*)&F[(size_t)kr*NN + n0 + nc];
    na1 = *(const float4*)&F[(size_t)kr*NN + n0 + nc + 4];
    nb  = *(const float4*)&g_w1T[kr*128 + o0 + oc];
    *(float4*)&Ns[0][kr][nc]   = na0;
    *(float4*)&Ns[0][kr][nc+4] = na1;
    *(float4*)&Os[0][kr][oc]   = nb;
    __syncthreads();
    int buf = 0;
    #pragma unroll 1
    for (int kb = 0; kb < 8; kb++) {
        bool has = kb < 7;
        if (has) {
            int kk = (kb+1)*16 + kr;
            na0 = *(const float4*)&F[(size_t)kk*NN + n0 + nc];
            na1 = *(const float4*)&F[(size_t)kk*NN + n0 + nc + 4];
            nb  = *(const float4*)&g_w1T[kk*128 + o0 + oc];
        }
        #pragma unroll
        for (int k = 0; k < 16; k++) {
            float4 a0 = *(const float4*)&Ns[buf][k][tr];
            float4 a1 = *(const float4*)&Ns[buf][k][tr+4];
            float4 bq = *(const float4*)&Os[buf][k][tc];
            float ar[8] = {a0.x,a0.y,a0.z,a0.w,a1.x,a1.y,a1.z,a1.w};
            float br[4] = {bq.x,bq.y,bq.z,bq.w};
            #pragma unroll
            for (int i = 0; i < 8; i++)
                #pragma unroll
                for (int j = 0; j < 4; j++)
                    acc[i][j] = fmaf(ar[i], br[j], acc[i][j]);
        }
        if (has) {
            int nbuf = buf^1;
            *(float4*)&Ns[nbuf][kr][nc]   = na0;
            *(float4*)&Ns[nbuf][kr][nc+4] = na1;
            *(float4*)&Os[nbuf][kr][oc]   = nb;
            __syncthreads();
            buf = nbuf;
        }
    }
    float* Gp = g_G + ((size_t)b*NN + n0 + tr)*128 + o0 + tc;
    #pragma unroll
    for (int i = 0; i < 8; i++) {
        float4 v = {acc[i][0], acc[i][1], acc[i][2], acc[i][3]};
        *(float4*)(Gp + (size_t)i*128) = v;
    }
}

// ---------------- combine v2: block = 32 corners, coalesced h1T row writes ----------------
__global__ void __launch_bounds__(256) combine_kernel(const float* __restrict__ w1,
                                                      const float* __restrict__ b1)
{
    __shared__ float wr0[128], wr1[128], wr2[128], sb[128];
    __shared__ float tr[128][33];
    int tid = threadIdx.x, lane = tid & 31, wid = tid >> 5;
    if (tid < 128) {
        const float* wrow = w1 + tid*131;
        wr0[tid] = wrow[0]; wr1[tid] = wrow[1]; wr2[tid] = wrow[2];
        sb[tid]  = b1[tid];
    }
    __syncthreads();
    int m0 = blockIdx.x*32;
    #pragma unroll 1
    for (int cc = 0; cc < 4; cc++) {
        int ml = wid*4 + cc;                         // 0..31 local corner
        int m  = m0 + ml;
        int b = m >> 13, mb = m & 8191;
        size_t base3 = ((size_t)b*M_TOT + mb)*3;
        int i0 = g_nni[base3+0], i1 = g_nni[base3+1], i2 = g_nni[base3+2];
        float w0 = g_nnw[base3+0], w1w = g_nnw[base3+1], w2w = g_nnw[base3+2];
        float rx = g_rel[(size_t)m*3+0], ry = g_rel[(size_t)m*3+1], rz = g_rel[(size_t)m*3+2];
        const float* G0 = g_G + ((size_t)b*NN + i0)*128;
        const float* G1 = g_G + ((size_t)b*NN + i1)*128;
        const float* G2 = g_G + ((size_t)b*NN + i2)*128;
        int c0 = lane*4;
        float4 a  = *(const float4*)(G0 + c0);
        float4 bq = *(const float4*)(G1 + c0);
        float4 cq = *(const float4*)(G2 + c0);
        float va[4] = {a.x,a.y,a.z,a.w};
        float vb[4] = {bq.x,bq.y,bq.z,bq.w};
        float vc[4] = {cq.x,cq.y,cq.z,cq.w};
        #pragma unroll
        for (int j = 0; j < 4; j++) {
            int o = c0 + j;
            float acc = w0*va[j] + w1w*vb[j] + w2w*vc[j];
            acc = fmaf(rx, wr0[o], acc);
            acc = fmaf(ry, wr1[o], acc);
            acc = fmaf(rz, wr2[o], acc);
            tr[o][ml] = fmaxf(acc + sb[o], 0.0f);
        }
    }
    __syncthreads();
    int c = tid >> 1, base = (tid & 1)*16;
    float* dst = &g_h1T[(size_t)c*MG + m0 + base];
    #pragma unroll
    for (int q = 0; q < 4; q++) {
        float4 v = {tr[c][base+q*4+0], tr[c][base+q*4+1], tr[c][base+q*4+2], tr[c][base+q*4+3]};
        *(float4*)(dst + q*4) = v;
    }
}

// ---------------- gemm2 (tf32 tensor-core) + fused relu + maxpool over 64 ----------------
__global__ void __launch_bounds__(256) gemm2_pool_kernel(const float* __restrict__ bias)
{
    __shared__ float As[2][16][132];     // [k][m], padded
    __shared__ float Bs[2][16][68];      // [k][o], padded
    __shared__ int spool[128];           // [2 pool-groups][64 o]
    int m0 = blockIdx.x*128, o0 = blockIdx.y*64;
    int tid = threadIdx.x, lane = tid & 31, wid = tid >> 5;
    int wm = wid >> 1, wn = wid & 1;
    int kr = tid >> 4, c16 = tid & 15;
    if (tid < 128) spool[tid] = 0;

    float acc[2][4][4] = {};

    {
        const float* ap = &g_h1T[(size_t)kr*MG + m0 + c16*8];
        float4 a0 = *(const float4*)ap;
        float4 a1 = *(const float4*)(ap + 4);
        float* d = &As[0][kr][c16*8];
        d[0]=tf32r(a0.x); d[1]=tf32r(a0.y); d[2]=tf32r(a0.z); d[3]=tf32r(a0.w);
        d[4]=tf32r(a1.x); d[5]=tf32r(a1.y); d[6]=tf32r(a1.z); d[7]=tf32r(a1.w);
        float4 bv = *(const float4*)&g_w2T[kr*256 + o0 + c16*4];
        float* e = &Bs[0][kr][c16*4];
        e[0]=tf32r(bv.x); e[1]=tf32r(bv.y); e[2]=tf32r(bv.z); e[3]=tf32r(bv.w);
    }
    __syncthreads();

    int buf = 0;
    int lk = lane & 3, lr = lane >> 2;
    #pragma unroll 1
    for (int kb = 0; kb < 8; kb++) {
        bool has = kb < 7;
        float4 na0, na1, nb;
        if (has) {
            int kk = (kb+1)*16 + kr;
            const float* ap = &g_h1T[(size_t)kk*MG + m0 + c16*8];
            na0 = *(const float4*)ap;
            na1 = *(const float4*)(ap + 4);
            nb  = *(const float4*)&g_w2T[kk*256 + o0 + c16*4];
        }
        #pragma unroll
        for (int ks = 0; ks < 2; ks++) {
            int klo = ks*8 + lk;
            uint32_t afr[2][4];
            #pragma unroll
            for (int mt = 0; mt < 2; mt++) {
                int mr = wm*32 + mt*16 + lr;
                afr[mt][0] = __float_as_uint(As[buf][klo  ][mr]);
                afr[mt][1] = __float_as_uint(As[buf][klo  ][mr+8]);
                afr[mt][2] = __float_as_uint(As[buf][klo+4][mr]);
                afr[mt][3] = __float_as_uint(As[buf][klo+4][mr+8]);
            }
            uint32_t bfr[4][2];
            #pragma unroll
            for (int nt = 0; nt < 4; nt++) {
                int nr = wn*32 + nt*8 + lr;
                bfr[nt][0] = __float_as_uint(Bs[buf][klo  ][nr]);
                bfr[nt][1] = __float_as_uint(Bs[buf][klo+4][nr]);
            }
            #pragma unroll
            for (int mt = 0; mt < 2; mt++)
                #pragma unroll
                for (int nt = 0; nt < 4; nt++)
                    mma_tf32(acc[mt][nt], afr[mt], bfr[nt]);
        }
        if (has) {
            int nbuf = buf^1;
            float* d = &As[nbuf][kr][c16*8];
            d[0]=tf32r(na0.x); d[1]=tf32r(na0.y); d[2]=tf32r(na0.z); d[3]=tf32r(na0.w);
            d[4]=tf32r(na1.x); d[5]=tf32r(na1.y); d[6]=tf32r(na1.z); d[7]=tf32r(na1.w);
            float* e = &Bs[nbuf][kr][c16*4];
            e[0]=tf32r(nb.x); e[1]=tf32r(nb.y); e[2]=tf32r(nb.z); e[3]=tf32r(nb.w);
            __syncthreads();
            buf = nbuf;
        }
    }

    int grp = wm >> 1;
    #pragma unroll
    for (int nt = 0; nt < 4; nt++) {
        int c0 = wn*32 + nt*8 + (lane & 3)*2;
        float b0v = bias[o0 + c0], b1v = bias[o0 + c0 + 1];
        float p0v = 0.0f, p1v = 0.0f;
        #pragma unroll
        for (int mt = 0; mt < 2; mt++) {
            p0v = fmaxf(p0v, acc[mt][nt][0] + b0v);
            p0v = fmaxf(p0v, acc[mt][nt][2] + b0v);
            p1v = fmaxf(p1v, acc[mt][nt][1] + b1v);
            p1v = fmaxf(p1v, acc[mt][nt][3] + b1v);
        }
        atomicMax(&spool[grp*64 + c0],     __float_as_int(p0v));
        atomicMax(&spool[grp*64 + c0 + 1], __float_as_int(p1v));
    }
    __syncthreads();
    if (tid < 128) {
        int g = tid >> 6, ol = tid & 63;
        int b  = m0 >> 13;
        int p0 = (m0 >> 6) & 127;
        g_pool[((size_t)b*256 + o0 + ol)*NPT + p0 + g] = __int_as_float(spool[g*64 + ol]);
    }
}

// ---------------- fused linear + train-mode BN + relu ----------------
__global__ void lin_bn_kernel(const float* __restrict__ W, const float* __restrict__ bias,
                              const float* __restrict__ gam, const float* __restrict__ bet,
                              int stage)
{
    int o = blockIdx.x, tid = threadIdx.x;            // 256 threads = (b,p)
    int b = tid >> 7, p = tid & 127;
    int K = stage ? 128 : 256;
    const float* X = stage ? g_z0 : g_pool;
    __shared__ float ws[256];
    if (tid < K) ws[tid] = W[o*K + tid];
    __syncthreads();
    const float* Xb = X + (size_t)b*K*NPT + p;
    float acc = bias[o];
    #pragma unroll 8
    for (int c = 0; c < K; c++) acc = fmaf(ws[c], Xb[(size_t)c*NPT], acc);
    __shared__ float red[256];
    red[tid] = acc; __syncthreads();
    #pragma unroll
    for (int s = 128; s > 0; s >>= 1) { if (tid < s) red[tid] += red[tid+s]; __syncthreads(); }
    float mean = red[0] * (1.0f/256.0f);
    __syncthreads();
    float d = acc - mean;
    red[tid] = d*d; __syncthreads();
    #pragma unroll
    for (int s = 128; s > 0; s >>= 1) { if (tid < s) red[tid] += red[tid+s]; __syncthreads(); }
    float var = red[0] * (1.0f/256.0f);
    float z = d * rsqrtf(var + 1e-5f) * gam[o] + bet[o];
    float* Y = stage ? g_z1 : g_z0;
    Y[((size_t)b*128 + o)*NPT + p] = fmaxf(z, 0.0f);
}

__global__ void final_kernel(const float* __restrict__ W, const float* __restrict__ bias,
                             float* __restrict__ out)
{
    int b = blockIdx.x, p = threadIdx.x;
    const float* Z = g_z1 + (size_t)b*128*NPT;
    float acc = bias[0];
    #pragma unroll 8
    for (int c = 0; c < 128; c++) acc = fmaf(W[c], Z[(size_t)c*NPT + p], acc);
    out[b*NPT + p] = acc;
}

// ---------------- launch ----------------
extern "C" void kernel_launch(void* const* d_in, const int* in_sizes, int n_in,
                              void* d_out, int out_size)
{
    const float* oxyz  = (const float*)d_in[0];
    const float* ofeat = (const float*)d_in[1];
    const float* cand  = (const float*)d_in[2];
    // d_in[3] = pred_cls (unused)
    const float* poff  = (const float*)d_in[4];
    const float* pacls = (const float*)d_in[5];
    const float* pares = (const float*)d_in[6];
    const float* w1    = (const float*)d_in[7];
    const float* b1    = (const float*)d_in[8];
    const float* w2    = (const float*)d_in[9];
    const float* b2    = (const float*)d_in[10];
    const float* wi0   = (const float*)d_in[11];
    const float* bi0   = (const float*)d_in[12];
    const float* gi0   = (const float*)d_in[13];
    const float* bei0  = (const float*)d_in[14];
    const float* wi1   = (const float*)d_in[15];
    const float* bi1   = (const float*)d_in[16];
    const float* gi1   = (const float*)d_in[17];
    const float* bei1  = (const float*)d_in[18];
    const float* wi2   = (const float*)d_in[19];
    const float* bi2   = (const float*)d_in[20];
    float* out = (float*)d_out;

    setup_kernel<<<320, 256>>>(cand, poff, pacls, pares, oxyz, w1, w2);  // #1
    prune_kernel<<<256, 256>>>(oxyz);                                    // #2
    threenn_part_kernel<<<dim3(512, NSEG), 256>>>();                     // #3
    merge_kernel<<<64, 256>>>(oxyz);                                     // #4
    gemmG_kernel<<<dim3(64, 2, 2), 256>>>(ofeat);                        // #5
    combine_kernel<<<512, 256>>>(w1, b1);                                // #6
    gemm2_pool_kernel<<<dim3(128, 4), 256>>>(b2);                        // #7
    lin_bn_kernel<<<128, 256>>>(wi0, bi0, gi0, bei0, 0);                 // #8
    lin_bn_kernel<<<128, 256>>>(wi1, bi1, gi1, bei1, 1);                 // #9
    final_kernel<<<2, 128>>>(wi2, bi2, out);                             // #10
}